// round 12
// baseline (speedup 1.0000x reference)
#include <cuda_runtime.h>
#include <cuda_bf16.h>
#include <math.h>
#include <stdint.h>

#define BATCH 4
#define CCH 256
#define HWN 4096
#define NTOK 16384          // BATCH*HWN
#define CHW (CCH*HWN)
#define TOTAL (BATCH*CHW)
#define EPS_GN 1e-5f
#define LDT 40              // padded smem row length (bf16) for 32-wide K tile
#define NPART 32            // n-tiles per batch (4096/128)
#define ATP 17              // attn smem col pad (16 tokens + 1)

// ---------------- scratch (device globals) ------------------------------------
__device__ __nv_bfloat16 g_Yqk[(size_t)512 * NTOK];  // rows 0-255 q, 256-511 k (bf16)
__device__ float g_Yv[(size_t)256 * NTOK];           // v fp32 channel-major
__device__ float g_pos[TOTAL];                       // NCHW positional branch output
__device__ float g_Z[(size_t)CCH * NTOK];            // [256][16384] channel-major
__device__ float g_part[3][32][NPART][2];            // stats partials from GEMM epilogues
__device__ __nv_bfloat16 g_Whi[768 * 256], g_Wlo[768 * 256];
__device__ __nv_bfloat16 g_Wphi[256 * 256], g_Wplo[256 * 256];
__device__ __nv_bfloat16 g_Xhi[(size_t)NTOK * 256], g_Xlo[(size_t)NTOK * 256];
__device__ __nv_bfloat16 g_Uhi[(size_t)NTOK * 256], g_Ulo[(size_t)NTOK * 256];

// ---------------- helpers ------------------------------------------------------
__device__ __forceinline__ uint32_t smem_u32(const void* p) {
    return (uint32_t)__cvta_generic_to_shared(p);
}
__device__ __forceinline__ unsigned short f2bf_us(float v) {
    __nv_bfloat16 b = __float2bfloat16(v);
    return *reinterpret_cast<unsigned short*>(&b);
}
__device__ __forceinline__ uint32_t pack2bf(float a, float b) {
    return ((uint32_t)f2bf_us(b) << 16) | f2bf_us(a);
}
__device__ __forceinline__ void cp_async16(uint32_t s, const void* g) {
    asm volatile("cp.async.cg.shared.global [%0], [%1], 16;" :: "r"(s), "l"(g));
}
__device__ __forceinline__ void cp_commit() {
    asm volatile("cp.async.commit_group;");
}
__device__ __forceinline__ void ldsm_x4(uint32_t* r, uint32_t a) {
    asm volatile("ldmatrix.sync.aligned.m8n8.x4.shared.b16 {%0,%1,%2,%3}, [%4];"
                 : "=r"(r[0]), "=r"(r[1]), "=r"(r[2]), "=r"(r[3]) : "r"(a));
}
__device__ __forceinline__ void ldsm_x2(uint32_t* r, uint32_t a) {
    asm volatile("ldmatrix.sync.aligned.m8n8.x2.shared.b16 {%0,%1}, [%2];"
                 : "=r"(r[0]), "=r"(r[1]) : "r"(a));
}
__device__ __forceinline__ void mma_bf16(float* c, const uint32_t* a, const uint32_t* b) {
    asm volatile(
        "mma.sync.aligned.m16n8k16.row.col.f32.bf16.bf16.f32 "
        "{%0,%1,%2,%3}, {%4,%5,%6,%7}, {%8,%9}, {%0,%1,%2,%3};"
        : "+f"(c[0]), "+f"(c[1]), "+f"(c[2]), "+f"(c[3])
        : "r"(a[0]), "r"(a[1]), "r"(a[2]), "r"(a[3]), "r"(b[0]), "r"(b[1]));
}

// ---------------- W -> bf16 hi/lo (K-major already) ---------------------------
__global__ void convert_w_kernel(const float* __restrict__ wq, const float* __restrict__ wk,
                                 const float* __restrict__ wv, const float* __restrict__ wp) {
    int i = blockIdx.x * 256 + threadIdx.x;  // 0..262143
    float v;
    __nv_bfloat16 *hi, *lo;
    int o;
    if (i < 65536)        { v = wq[i];          o = i;          hi = g_Whi;  lo = g_Wlo; }
    else if (i < 131072)  { v = wk[i - 65536];  o = i;          hi = g_Whi;  lo = g_Wlo; }
    else if (i < 196608)  { v = wv[i - 131072]; o = i;          hi = g_Whi;  lo = g_Wlo; }
    else                  { v = wp[i - 196608]; o = i - 196608; hi = g_Wphi; lo = g_Wplo; }
    __nv_bfloat16 h = __float2bfloat16(v);
    hi[o] = h;
    lo[o] = __float2bfloat16(v - __bfloat162float(h));
}

// ---------------- transpose [c][hw] fp32 -> token-major bf16 hi/lo -------------
__global__ void transpose_convert_kernel(const float* __restrict__ src, int c_stride, int b_stride,
                                         __nv_bfloat16* __restrict__ dhi,
                                         __nv_bfloat16* __restrict__ dlo) {
    __shared__ float t[32][33];
    const int hw0 = blockIdx.x * 32, c0 = blockIdx.y * 32, b = blockIdx.z;
    const int tid = threadIdx.x;
    const int rl = tid >> 3, q = tid & 7;
    float4 v = *(const float4*)(src + (size_t)b * b_stride + (size_t)(c0 + rl) * c_stride + hw0 + q * 4);
    t[rl][q * 4 + 0] = v.x; t[rl][q * 4 + 1] = v.y;
    t[rl][q * 4 + 2] = v.z; t[rl][q * 4 + 3] = v.w;
    __syncthreads();
    const int n = b * HWN + hw0 + rl;
    ushort4 hs, ls;
    float f0 = t[q * 4 + 0][rl], f1 = t[q * 4 + 1][rl];
    float f2 = t[q * 4 + 2][rl], f3 = t[q * 4 + 3][rl];
    hs.x = f2bf_us(f0); hs.y = f2bf_us(f1); hs.z = f2bf_us(f2); hs.w = f2bf_us(f3);
    ls.x = f2bf_us(f0 - __bfloat162float(__float2bfloat16(f0)));
    ls.y = f2bf_us(f1 - __bfloat162float(__float2bfloat16(f1)));
    ls.z = f2bf_us(f2 - __bfloat162float(__float2bfloat16(f2)));
    ls.w = f2bf_us(f3 - __bfloat162float(__float2bfloat16(f3)));
    *(ushort4*)(dhi + (size_t)n * 256 + c0 + q * 4) = hs;
    *(ushort4*)(dlo + (size_t)n * 256 + c0 + q * 4) = ls;
}

// ---------------- mma.sync GEMM + fused GN stats partials ----------------------
// gemm1 q,k blocks (y<4): single bf16 pass, bf16 output to g_Yqk.
// gemm1 v blocks (y=4,5): 3-pass split, fp32 to g_Yv.
// gemm2: 3-pass split, fp32 + bias to out.
__global__ __launch_bounds__(256) void mma_gemm_kernel(
    const __nv_bfloat16* __restrict__ Ahi, const __nv_bfloat16* __restrict__ Alo,
    const __nv_bfloat16* __restrict__ Bhi, const __nv_bfloat16* __restrict__ Blo,
    float* __restrict__ out, const float* __restrict__ bias, int gemm_id) {
    extern __shared__ __nv_bfloat16 smT[];   // [2 buf][4 mat][128*LDT]
    __shared__ float sred[8][4];
    const int tid = threadIdx.x;
    const int lane = tid & 31;
    const int wid = tid >> 5;
    const int wm = wid >> 2;
    const int wn = wid & 3;
    const int m0 = blockIdx.y * 128;
    const int n0 = blockIdx.x * 128;
    const int qk = (gemm_id == 0 && blockIdx.y < 4);
    const int npass = qk ? 1 : 3;

    float acc[4][4][4];
#pragma unroll
    for (int i = 0; i < 4; i++)
#pragma unroll
        for (int j = 0; j < 4; j++)
#pragma unroll
            for (int r = 0; r < 4; r++) acc[i][j][r] = 0.f;

    const int lrow = tid >> 1;
    const int lch2 = (tid & 1) * 2;

#define TILE_BASE(buf, mat) (smT + ((buf) * 4 + (mat)) * (128 * LDT))
#define LOAD_STAGE(buf, kc)                                                             \
    do {                                                                                \
        const int k0 = (kc) * 32;                                                       \
        _Pragma("unroll")                                                               \
        for (int mat = 0; mat < 4; mat++) {                                             \
            if (npass == 1 && (mat == 1 || mat == 3)) continue;                         \
            const __nv_bfloat16* src =                                                  \
                ((mat == 0) ? Ahi : (mat == 1) ? Alo : (mat == 2) ? Bhi : Blo) +        \
                (size_t)(((mat < 2) ? m0 : n0) + lrow) * 256 + k0 + lch2 * 8;           \
            uint32_t d = smem_u32(TILE_BASE(buf, mat) + lrow * LDT + lch2 * 8);         \
            cp_async16(d, src);                                                         \
            cp_async16(d + 16, src + 8);                                                \
        }                                                                               \
        cp_commit();                                                                    \
    } while (0)

    LOAD_STAGE(0, 0);

    int buf = 0;
    for (int kc = 0; kc < 8; kc++) {
        if (kc + 1 < 8) {
            LOAD_STAGE(buf ^ 1, kc + 1);
            asm volatile("cp.async.wait_group 1;");
        } else {
            asm volatile("cp.async.wait_group 0;");
        }
        __syncthreads();

#pragma unroll 3
        for (int pass = 0; pass < npass; pass++) {
            const __nv_bfloat16* At = TILE_BASE(buf, (pass == 2) ? 1 : 0);
            const __nv_bfloat16* Bt = TILE_BASE(buf, (pass == 1) ? 3 : 2);
#pragma unroll
            for (int ks = 0; ks < 2; ks++) {
                uint32_t afr[4][4];
#pragma unroll
                for (int i = 0; i < 4; i++) {
                    uint32_t a = smem_u32(&At[(wm * 64 + i * 16 + (lane & 15)) * LDT +
                                             ((lane >> 4) * 8 + ks * 16)]);
                    ldsm_x4(afr[i], a);
                }
                uint32_t bfr[4][2];
#pragma unroll
                for (int j = 0; j < 4; j++) {
                    int l2 = lane & 15;
                    uint32_t a = smem_u32(&Bt[(wn * 32 + j * 8 + (l2 & 7)) * LDT +
                                             (((l2 >> 3) & 1) * 8 + ks * 16)]);
                    ldsm_x2(bfr[j], a);
                }
#pragma unroll
                for (int i = 0; i < 4; i++)
#pragma unroll
                    for (int j = 0; j < 4; j++) mma_bf16(acc[i][j], afr[i], bfr[j]);
            }
        }
        __syncthreads();
        buf ^= 1;
    }
#undef LOAD_STAGE
#undef TILE_BASE

    float s[2] = {0.f, 0.f}, s2[2] = {0.f, 0.f};
#pragma unroll
    for (int i = 0; i < 4; i++) {
        const int row = m0 + wm * 64 + i * 16 + (lane >> 2);
        const int gh = i >> 1;
        const float b0v = (gemm_id == 1) ? bias[row] : 0.f;
        const float b1v = (gemm_id == 1) ? bias[row + 8] : 0.f;
#pragma unroll
        for (int j = 0; j < 4; j++) {
            const int col = n0 + wn * 32 + j * 8 + (lane & 3) * 2;
            float v0x = acc[i][j][0] + b0v, v0y = acc[i][j][1] + b0v;
            float v1x = acc[i][j][2] + b1v, v1y = acc[i][j][3] + b1v;
            s[gh] += (v0x + v0y) + (v1x + v1y);
            s2[gh] += v0x * v0x + v0y * v0y + v1x * v1x + v1y * v1y;
            if (qk) {
                *(uint32_t*)(g_Yqk + (size_t)row * NTOK + col) = pack2bf(v0x, v0y);
                *(uint32_t*)(g_Yqk + (size_t)(row + 8) * NTOK + col) = pack2bf(v1x, v1y);
            } else if (gemm_id == 0) {
                float* vout = g_Yv + (size_t)(row - 512) * NTOK;
                *(float2*)(vout + col) = make_float2(v0x, v0y);
                *(float2*)(vout + (size_t)8 * NTOK + col) = make_float2(v1x, v1y);
            } else {
                *(float2*)(out + (size_t)row * NTOK + col) = make_float2(v0x, v0y);
                *(float2*)(out + (size_t)(row + 8) * NTOK + col) = make_float2(v1x, v1y);
            }
        }
    }

    int slot = (gemm_id == 0) ? (qk ? (int)(blockIdx.y >> 1) : -1) : 2;
    if (slot < 0) return;
    const int group_base = (gemm_id == 0) ? (blockIdx.y & 1) * 4 : blockIdx.y * 4;

#pragma unroll
    for (int off = 16; off > 0; off >>= 1) {
        s[0] += __shfl_xor_sync(0xffffffffu, s[0], off);
        s[1] += __shfl_xor_sync(0xffffffffu, s[1], off);
        s2[0] += __shfl_xor_sync(0xffffffffu, s2[0], off);
        s2[1] += __shfl_xor_sync(0xffffffffu, s2[1], off);
    }
    if (lane == 0) {
        sred[wid][0] = s[0]; sred[wid][1] = s[1];
        sred[wid][2] = s2[0]; sred[wid][3] = s2[1];
    }
    __syncthreads();
    if (tid < 4) {
        const int wmm = tid >> 1, gh = tid & 1;
        float ss = 0.f, ss2 = 0.f;
#pragma unroll
        for (int w = 0; w < 4; w++) {
            ss += sred[wmm * 4 + w][gh];
            ss2 += sred[wmm * 4 + w][2 + gh];
        }
        const int b = blockIdx.x >> 5;
        const int bxl = blockIdx.x & 31;
        const int pair = b * 8 + group_base + wmm * 2 + gh;
        g_part[slot][pair][bxl][0] = ss;
        g_part[slot][pair][bxl][1] = ss2;
    }
}

// ---------------- fused dwconv 3x3 + GeLU + conv 3x3: 2 blocks per plane -------
// Block handles 32 output rows; x tile 36 rows (+2 halo each side), p1 34 rows.
__global__ __launch_bounds__(256) void dwconv_fused_kernel(
    const float* __restrict__ x,
    const float* __restrict__ dw1, const float* __restrict__ db1,
    const float* __restrict__ dw2, const float* __restrict__ db2) {
    __shared__ float xs[36 * 68];
    __shared__ float p1[34 * 68];
    const int blk = blockIdx.x;
    const int bc = blk >> 1;            // b*256 + c
    const int c = bc & 255;
    const int out0 = (blk & 1) * 32;    // first output row
    const float* xb = x + (size_t)bc * HWN;
    const int tid = threadIdx.x;

    for (int i = tid; i < 36 * 68; i += 256) xs[i] = 0.f;
    for (int i = tid; i < 34 * 68; i += 256) p1[i] = 0.f;
    float w1[9], w2[9];
#pragma unroll
    for (int i = 0; i < 9; i++) { w1[i] = dw1[c * 9 + i]; w2[i] = dw2[c * 9 + i]; }
    const float b1 = db1[c], b2 = db2[c];
    __syncthreads();

    // load x rows [out0-2, out0+34) into xs rows 0..35 (cols padded +1)
    for (int idx = tid; idx < 576; idx += 256) {
        int lr = idx >> 4;
        int gr = out0 - 2 + lr;
        int px4 = (idx & 15) * 4;
        if ((unsigned)gr < 64u) {
            float4 v = *(const float4*)(xb + gr * 64 + px4);
            float* d = &xs[lr * 68 + 1 + px4];
            d[0] = v.x; d[1] = v.y; d[2] = v.z; d[3] = v.w;
        }
    }
    __syncthreads();

    // phase 1: p1 local rows 0..33 = global rows out0-1 .. out0+32
    for (int idx = tid; idx < 544; idx += 256) {
        int lr = idx >> 4;
        int gp = out0 - 1 + lr;
        int px4 = (idx & 15) * 4;
        if ((unsigned)gp < 64u) {
            const float* base = &xs[lr * 68 + px4];
            float r0[6], r1[6], r2[6];
            *(float4*)&r0[0] = *(const float4*)(base);
            *(float2*)&r0[4] = *(const float2*)(base + 4);
            *(float4*)&r1[0] = *(const float4*)(base + 68);
            *(float2*)&r1[4] = *(const float2*)(base + 72);
            *(float4*)&r2[0] = *(const float4*)(base + 136);
            *(float2*)&r2[4] = *(const float2*)(base + 140);
            float* prow = &p1[lr * 68 + px4 + 1];
#pragma unroll
            for (int p = 0; p < 4; p++) {
                float acc = b1;
                acc = fmaf(r0[p],     w1[0], acc);
                acc = fmaf(r0[p + 1], w1[1], acc);
                acc = fmaf(r0[p + 2], w1[2], acc);
                acc = fmaf(r1[p],     w1[3], acc);
                acc = fmaf(r1[p + 1], w1[4], acc);
                acc = fmaf(r1[p + 2], w1[5], acc);
                acc = fmaf(r2[p],     w1[6], acc);
                acc = fmaf(r2[p + 1], w1[7], acc);
                acc = fmaf(r2[p + 2], w1[8], acc);
                prow[p] = 0.5f * acc * (1.f + erff(acc * 0.70710678118654752f));
            }
        }
    }
    __syncthreads();

    // phase 2: output rows out0..out0+31 (p1 local rows lr2..lr2+2)
    for (int idx = tid; idx < 512; idx += 256) {
        int lr2 = idx >> 4;
        int px4 = (idx & 15) * 4;
        const float* base = &p1[lr2 * 68 + px4];
        float r0[6], r1[6], r2[6];
        *(float4*)&r0[0] = *(const float4*)(base);
        *(float2*)&r0[4] = *(const float2*)(base + 4);
        *(float4*)&r1[0] = *(const float4*)(base + 68);
        *(float2*)&r1[4] = *(const float2*)(base + 72);
        *(float4*)&r2[0] = *(const float4*)(base + 136);
        *(float2*)&r2[4] = *(const float2*)(base + 140);
        float4 ov;
        float* po = &ov.x;
#pragma unroll
        for (int p = 0; p < 4; p++) {
            float acc = b2;
            acc = fmaf(r0[p],     w2[0], acc);
            acc = fmaf(r0[p + 1], w2[1], acc);
            acc = fmaf(r0[p + 2], w2[2], acc);
            acc = fmaf(r1[p],     w2[3], acc);
            acc = fmaf(r1[p + 1], w2[4], acc);
            acc = fmaf(r1[p + 2], w2[5], acc);
            acc = fmaf(r2[p],     w2[6], acc);
            acc = fmaf(r2[p + 1], w2[7], acc);
            acc = fmaf(r2[p + 2], w2[8], acc);
            po[p] = acc;
        }
        *(float4*)(g_pos + (size_t)bc * HWN + (out0 + lr2) * 64 + px4) = ov;
    }
}

// ---------------- attention: 16 tokens/block, fused single butterfly -----------
__global__ __launch_bounds__(512) void attn_kernel(
    const float* __restrict__ gqg, const float* __restrict__ gqb,
    const float* __restrict__ gkg, const float* __restrict__ gkb) {
    extern __shared__ float smf[];
    __shared__ float sstat[2][8][2];  // [slot q/k][head][mean,rstd]
    float* smq = smf;                 // [256][ATP]
    float* smk = smf + 256 * ATP;
    float* smv = smf + 2 * 256 * ATP;
    float* smp = smf + 3 * 256 * ATP; // pos tile
    const int tid = threadIdx.x;
    const int warp = tid >> 5;        // 0..15 = token
    const int lane = tid & 31;
    const int n0 = blockIdx.x * 16;
    const int b = n0 >> 12;
    const int hw0 = n0 & 4095;

    if (warp < 16) {
        const int sl = warp >> 3;
        const int h = warp & 7;
        float s = g_part[sl][b * 8 + h][lane][0];
        float s2 = g_part[sl][b * 8 + h][lane][1];
#pragma unroll
        for (int off = 16; off > 0; off >>= 1) {
            s += __shfl_xor_sync(0xffffffffu, s, off);
            s2 += __shfl_xor_sync(0xffffffffu, s2, off);
        }
        if (lane == 0) {
            const float inv = 1.f / 131072.f;
            float mean = s * inv;
            float var = s2 * inv - mean * mean;
            sstat[sl][h][0] = mean;
            sstat[sl][h][1] = rsqrtf(var + EPS_GN);
        }
    }

    // q,k bf16: 2 tensors x 256 rows x 2 uint4 (8 bf16) slots = 1024 slots
#pragma unroll
    for (int r = 0; r < 2; r++) {
        int slot = tid + r * 512;
        int tens = slot >> 9;             // 0=q, 1=k
        int row = (slot >> 1) & 255;
        int half = (slot & 1) * 8;
        uint4 u = *(const uint4*)(g_Yqk + (size_t)(tens * 256 + row) * NTOK + n0 + half);
        const __nv_bfloat16* bp16 = (const __nv_bfloat16*)&u;
        float* dst = smf + tens * (256 * ATP) + row * ATP + half;
#pragma unroll
        for (int e = 0; e < 8; e++) dst[e] = __bfloat162float(bp16[e]);
    }
    // v fp32: 256 rows x 4 float4 = 1024 slots
#pragma unroll
    for (int r = 0; r < 2; r++) {
        int slot = tid + r * 512;
        int row = slot >> 2;
        int q4 = (slot & 3) * 4;
        float4 v = *(const float4*)(g_Yv + (size_t)row * NTOK + n0 + q4);
        float* dst = smv + row * ATP + q4;
        dst[0] = v.x; dst[1] = v.y; dst[2] = v.z; dst[3] = v.w;
    }
    // pos fp32 (NCHW)
#pragma unroll
    for (int r = 0; r < 2; r++) {
        int slot = tid + r * 512;
        int row = slot >> 2;
        int q4 = (slot & 3) * 4;
        float4 v = *(const float4*)(g_pos + (size_t)b * CHW + (size_t)row * HWN + hw0 + q4);
        float* dst = smp + row * ATP + q4;
        dst[0] = v.x; dst[1] = v.y; dst[2] = v.z; dst[3] = v.w;
    }
    __syncthreads();

    const float scale = 0.17677669529663687f;  // 1/sqrt(32)
    float oacc[8];
#pragma unroll 1
    for (int h = 0; h < 8; h++) {
        const int c = h * 32 + lane;
        float q = smq[c * ATP + warp];
        float k = smk[c * ATP + warp];
        float vv = smv[c * ATP + warp];
        q = (q - sstat[0][h][0]) * sstat[0][h][1] * gqg[c] + gqb[c];
        k = (k - sstat[1][h][0]) * sstat[1][h][1] * gkg[c] + gkb[c];

        const float k2 = k * k;
        const float k3 = k2 * k;
        const float k4 = k2 * k2;
        float sq = q * q;
        float m1 = k, m2 = k2, m3 = k3, m4 = k4;
        float w0 = vv, w1 = k * vv, w2 = k2 * vv, w3 = k3 * vv, w4 = k4 * vv;
#pragma unroll
        for (int off = 16; off > 0; off >>= 1) {
            sq += __shfl_xor_sync(0xffffffffu, sq, off);
            m1 += __shfl_xor_sync(0xffffffffu, m1, off);
            m2 += __shfl_xor_sync(0xffffffffu, m2, off);
            m3 += __shfl_xor_sync(0xffffffffu, m3, off);
            m4 += __shfl_xor_sync(0xffffffffu, m4, off);
            w0 += __shfl_xor_sync(0xffffffffu, w0, off);
            w1 += __shfl_xor_sync(0xffffffffu, w1, off);
            w2 += __shfl_xor_sync(0xffffffffu, w2, off);
            w3 += __shfl_xor_sync(0xffffffffu, w3, off);
            w4 += __shfl_xor_sync(0xffffffffu, w4, off);
        }
        const float rq = 1.f / fmaxf(sqrtf(sq), 1e-12f);
        const float rk = 1.f / fmaxf(sqrtf(m2), 1e-12f);
        const float rk2 = rk * rk, rk3 = rk2 * rk, rk4 = rk2 * rk2;
        const float s = q * rq * scale;

        const float c2 = 0.5f, c3 = 1.f / 6.f, c4 = 1.f / 24.f;
        const float a1 = m1 * rk, a2 = m2 * rk2, a3 = m3 * rk3, a4 = m4 * rk4;
        const float b1m = w1 * rk, b2 = w2 * rk2, b3 = w3 * rk3, b4 = w4 * rk4;
        float num = fmaf(s, fmaf(s, fmaf(s, fmaf(s, b4 * c4, b3 * c3), b2 * c2), b1m), w0);
        float den = fmaf(s, fmaf(s, fmaf(s, fmaf(s, a4 * c4, a3 * c3), a2 * c2), a1), 32.f);
        oacc[h] = __fdividef(num, den) + smp[c * ATP + warp];
    }
#pragma unroll
    for (int h = 0; h < 8; h++) smq[(h * 32 + lane) * ATP + warp] = oacc[h];
    __syncthreads();

#pragma unroll
    for (int it = 0; it < 2; it++) {
        const int idx = tid + it * 512;
        const int j = idx >> 6;            // token 0..15
        const int c0 = (idx & 63) * 4;
        float f0 = smq[(c0 + 0) * ATP + j];
        float f1 = smq[(c0 + 1) * ATP + j];
        float f2 = smq[(c0 + 2) * ATP + j];
        float f3 = smq[(c0 + 3) * ATP + j];
        ushort4 hs, ls;
        hs.x = f2bf_us(f0); hs.y = f2bf_us(f1); hs.z = f2bf_us(f2); hs.w = f2bf_us(f3);
        ls.x = f2bf_us(f0 - __bfloat162float(__float2bfloat16(f0)));
        ls.y = f2bf_us(f1 - __bfloat162float(__float2bfloat16(f1)));
        ls.z = f2bf_us(f2 - __bfloat162float(__float2bfloat16(f2)));
        ls.w = f2bf_us(f3 - __bfloat162float(__float2bfloat16(f3)));
        const size_t n = (size_t)(n0 + j);
        *(ushort4*)(g_Uhi + n * 256 + c0) = hs;
        *(ushort4*)(g_Ulo + n * 256 + c0) = ls;
    }
}

// ---------------- final GN apply (stats reduced in-block) ----------------------
__global__ void gn_apply_kernel(const float* __restrict__ gamma,
                                const float* __restrict__ beta,
                                float* __restrict__ out) {
    __shared__ float sms[2];
    const int blk0 = blockIdx.x * 256;
    const int cB = blk0 >> 12;
    const int bB = ((blk0 & 4095) * 4) >> 12;
    if (threadIdx.x < 32) {
        const int lane = threadIdx.x;
        const int pair = bB * 8 + (cB >> 5);
        float s = g_part[2][pair][lane][0];
        float s2 = g_part[2][pair][lane][1];
#pragma unroll
        for (int off = 16; off > 0; off >>= 1) {
            s += __shfl_xor_sync(0xffffffffu, s, off);
            s2 += __shfl_xor_sync(0xffffffffu, s2, off);
        }
        if (lane == 0) {
            const float inv = 1.f / 131072.f;
            float mean = s * inv;
            float var = s2 * inv - mean * mean;
            sms[0] = mean;
            sms[1] = rsqrtf(var + EPS_GN);
        }
    }
    __syncthreads();
    const int idx4 = blk0 + threadIdx.x;
    const int c = idx4 >> 12;
    const int n = (idx4 & 4095) * 4;
    const int b = n >> 12;
    const float mean = sms[0], rstd = sms[1];
    const float ga = gamma[c], be = beta[c];
    float4 v = *(const float4*)(g_Z + (size_t)idx4 * 4);
    v.x = (v.x - mean) * rstd * ga + be;
    v.y = (v.y - mean) * rstd * ga + be;
    v.z = (v.z - mean) * rstd * ga + be;
    v.w = (v.w - mean) * rstd * ga + be;
    *(float4*)(out + (size_t)b * CHW + (size_t)c * HWN + (n & 4095)) = v;
}

// ---------------- launcher -----------------------------------------------------
extern "C" void kernel_launch(void* const* d_in, const int* in_sizes, int n_in,
                              void* d_out, int out_size) {
    const float* x        = (const float*)d_in[0];
    const float* wq       = (const float*)d_in[1];
    const float* gq_gamma = (const float*)d_in[2];
    const float* gq_beta  = (const float*)d_in[3];
    const float* wk       = (const float*)d_in[4];
    const float* gk_gamma = (const float*)d_in[5];
    const float* gk_beta  = (const float*)d_in[6];
    const float* wv       = (const float*)d_in[7];
    const float* wp       = (const float*)d_in[8];
    const float* bp       = (const float*)d_in[9];
    const float* gp_gamma = (const float*)d_in[10];
    const float* gp_beta  = (const float*)d_in[11];
    const float* dw1      = (const float*)d_in[12];
    const float* db1      = (const float*)d_in[13];
    const float* dw2      = (const float*)d_in[14];
    const float* db2      = (const float*)d_in[15];
    float* out = (float*)d_out;

    const int GEMM_SMEM = 2 * 4 * 128 * LDT * 2;      // 81920
    const int ATTN_SMEM = 4 * 256 * ATP * 4;          // 69632
    static bool attr_set = false;
    if (!attr_set) {
        cudaFuncSetAttribute(attn_kernel, cudaFuncAttributeMaxDynamicSharedMemorySize, ATTN_SMEM);
        cudaFuncSetAttribute(mma_gemm_kernel, cudaFuncAttributeMaxDynamicSharedMemorySize, GEMM_SMEM);
        attr_set = true;
    }

    float *g_Z_p;
    __nv_bfloat16 *whi, *wlo, *wphi, *wplo, *xhi, *xlo, *uhi, *ulo;
    cudaGetSymbolAddress((void**)&g_Z_p, g_Z);
    cudaGetSymbolAddress((void**)&whi, g_Whi);
    cudaGetSymbolAddress((void**)&wlo, g_Wlo);
    cudaGetSymbolAddress((void**)&wphi, g_Wphi);
    cudaGetSymbolAddress((void**)&wplo, g_Wplo);
    cudaGetSymbolAddress((void**)&xhi, g_Xhi);
    cudaGetSymbolAddress((void**)&xlo, g_Xlo);
    cudaGetSymbolAddress((void**)&uhi, g_Uhi);
    cudaGetSymbolAddress((void**)&ulo, g_Ulo);

    // 1. weight + input conversion
    convert_w_kernel<<<1024, 256>>>(wq, wk, wv, wp);
    transpose_convert_kernel<<<dim3(128, 8, BATCH), 256>>>(x, HWN, CHW, xhi, xlo);
    // 2. QKV GEMM (q,k single-pass bf16 out; v 3-pass fp32; stats fused)
    mma_gemm_kernel<<<dim3(128, 6), 256, GEMM_SMEM>>>(whi, wlo, xhi, xlo, nullptr, nullptr, 0);
    // 3. fused positional path -> g_pos (2 blocks per plane)
    dwconv_fused_kernel<<<2048, 256>>>(x, dw1, db1, dw2, db2);
    // 4. attention (finalizes q/k stats in-block) + residual -> U bf16 hi/lo
    attn_kernel<<<1024, 512, ATTN_SMEM>>>(gq_gamma, gq_beta, gk_gamma, gk_beta);
    // 5. output projection GEMM (3-pass; z stats fused) -> g_Z [256][16384]
    mma_gemm_kernel<<<dim3(128, 2), 256, GEMM_SMEM>>>(wphi, wplo, uhi, ulo, g_Z_p, bp, 1);
    // 6. final group norm apply (finalizes z stats in-block)
    gn_apply_kernel<<<NTOK * 256 / 1024, 256>>>(gp_gamma, gp_beta, out);
}

// round 13
// speedup vs baseline: 1.0277x; 1.0277x over previous
#include <cuda_runtime.h>
#include <cuda_bf16.h>
#include <math.h>
#include <stdint.h>

#define BATCH 4
#define CCH 256
#define HWN 4096
#define NTOK 16384          // BATCH*HWN
#define CHW (CCH*HWN)
#define TOTAL (BATCH*CHW)
#define EPS_GN 1e-5f
#define LDT 40              // padded smem row length (bf16) for 32-wide K tile
#define NPART 32            // n-tiles per batch (4096/128)
#define ATP 17              // attn fp32 smem col pad (16 tokens + 1)
#define ATPB 18             // attn bf16 smem col pad (36-byte rows, conflict-free)

// ---------------- scratch (device globals) ------------------------------------
__device__ __nv_bfloat16 g_Yqk[(size_t)512 * NTOK];  // rows 0-255 q, 256-511 k (bf16)
__device__ float g_Yv[(size_t)256 * NTOK];           // v fp32 channel-major
__device__ float g_pos[TOTAL];                       // NCHW positional branch output
__device__ float g_Z[(size_t)CCH * NTOK];            // [256][16384] channel-major
__device__ float g_part[3][32][NPART][2];            // stats partials from GEMM epilogues
__device__ __nv_bfloat16 g_Whi[768 * 256], g_Wlo[768 * 256];
__device__ __nv_bfloat16 g_Wphi[256 * 256], g_Wplo[256 * 256];
__device__ __nv_bfloat16 g_Xhi[(size_t)NTOK * 256], g_Xlo[(size_t)NTOK * 256];
__device__ __nv_bfloat16 g_Uhi[(size_t)NTOK * 256], g_Ulo[(size_t)NTOK * 256];

// ---------------- helpers ------------------------------------------------------
__device__ __forceinline__ uint32_t smem_u32(const void* p) {
    return (uint32_t)__cvta_generic_to_shared(p);
}
__device__ __forceinline__ unsigned short f2bf_us(float v) {
    __nv_bfloat16 b = __float2bfloat16(v);
    return *reinterpret_cast<unsigned short*>(&b);
}
__device__ __forceinline__ float us2f(unsigned short u) {
    __nv_bfloat16 b = *reinterpret_cast<__nv_bfloat16*>(&u);
    return __bfloat162float(b);
}
__device__ __forceinline__ uint32_t pack2bf(float a, float b) {
    return ((uint32_t)f2bf_us(b) << 16) | f2bf_us(a);
}
__device__ __forceinline__ void cp_async16(uint32_t s, const void* g) {
    asm volatile("cp.async.cg.shared.global [%0], [%1], 16;" :: "r"(s), "l"(g));
}
__device__ __forceinline__ void cp_commit() {
    asm volatile("cp.async.commit_group;");
}
__device__ __forceinline__ void ldsm_x4(uint32_t* r, uint32_t a) {
    asm volatile("ldmatrix.sync.aligned.m8n8.x4.shared.b16 {%0,%1,%2,%3}, [%4];"
                 : "=r"(r[0]), "=r"(r[1]), "=r"(r[2]), "=r"(r[3]) : "r"(a));
}
__device__ __forceinline__ void ldsm_x2(uint32_t* r, uint32_t a) {
    asm volatile("ldmatrix.sync.aligned.m8n8.x2.shared.b16 {%0,%1}, [%2];"
                 : "=r"(r[0]), "=r"(r[1]) : "r"(a));
}
__device__ __forceinline__ void mma_bf16(float* c, const uint32_t* a, const uint32_t* b) {
    asm volatile(
        "mma.sync.aligned.m16n8k16.row.col.f32.bf16.bf16.f32 "
        "{%0,%1,%2,%3}, {%4,%5,%6,%7}, {%8,%9}, {%0,%1,%2,%3};"
        : "+f"(c[0]), "+f"(c[1]), "+f"(c[2]), "+f"(c[3])
        : "r"(a[0]), "r"(a[1]), "r"(a[2]), "r"(a[3]), "r"(b[0]), "r"(b[1]));
}

// ---------------- W -> bf16 hi/lo (K-major already) ---------------------------
__global__ void convert_w_kernel(const float* __restrict__ wq, const float* __restrict__ wk,
                                 const float* __restrict__ wv, const float* __restrict__ wp) {
    int i = blockIdx.x * 256 + threadIdx.x;  // 0..262143
    float v;
    __nv_bfloat16 *hi, *lo;
    int o;
    if (i < 65536)        { v = wq[i];          o = i;          hi = g_Whi;  lo = g_Wlo; }
    else if (i < 131072)  { v = wk[i - 65536];  o = i;          hi = g_Whi;  lo = g_Wlo; }
    else if (i < 196608)  { v = wv[i - 131072]; o = i;          hi = g_Whi;  lo = g_Wlo; }
    else                  { v = wp[i - 196608]; o = i - 196608; hi = g_Wphi; lo = g_Wplo; }
    __nv_bfloat16 h = __float2bfloat16(v);
    hi[o] = h;
    lo[o] = __float2bfloat16(v - __bfloat162float(h));
}

// ---------------- transpose [c][hw] fp32 -> token-major bf16 hi/lo -------------
__global__ void transpose_convert_kernel(const float* __restrict__ src, int c_stride, int b_stride,
                                         __nv_bfloat16* __restrict__ dhi,
                                         __nv_bfloat16* __restrict__ dlo) {
    __shared__ float t[32][33];
    const int hw0 = blockIdx.x * 32, c0 = blockIdx.y * 32, b = blockIdx.z;
    const int tid = threadIdx.x;
    const int rl = tid >> 3, q = tid & 7;
    float4 v = *(const float4*)(src + (size_t)b * b_stride + (size_t)(c0 + rl) * c_stride + hw0 + q * 4);
    t[rl][q * 4 + 0] = v.x; t[rl][q * 4 + 1] = v.y;
    t[rl][q * 4 + 2] = v.z; t[rl][q * 4 + 3] = v.w;
    __syncthreads();
    const int n = b * HWN + hw0 + rl;
    ushort4 hs, ls;
    float f0 = t[q * 4 + 0][rl], f1 = t[q * 4 + 1][rl];
    float f2 = t[q * 4 + 2][rl], f3 = t[q * 4 + 3][rl];
    hs.x = f2bf_us(f0); hs.y = f2bf_us(f1); hs.z = f2bf_us(f2); hs.w = f2bf_us(f3);
    ls.x = f2bf_us(f0 - __bfloat162float(__float2bfloat16(f0)));
    ls.y = f2bf_us(f1 - __bfloat162float(__float2bfloat16(f1)));
    ls.z = f2bf_us(f2 - __bfloat162float(__float2bfloat16(f2)));
    ls.w = f2bf_us(f3 - __bfloat162float(__float2bfloat16(f3)));
    *(ushort4*)(dhi + (size_t)n * 256 + c0 + q * 4) = hs;
    *(ushort4*)(dlo + (size_t)n * 256 + c0 + q * 4) = ls;
}

// ---------------- mma.sync GEMM + fused GN stats partials ----------------------
// gemm1 q,k blocks (y<4): single bf16 pass, bf16 output to g_Yqk.
// gemm1 v blocks (y=4,5): 3-pass split, fp32 to g_Yv.
// gemm2: 3-pass split, fp32 + bias to out.
__global__ __launch_bounds__(256) void mma_gemm_kernel(
    const __nv_bfloat16* __restrict__ Ahi, const __nv_bfloat16* __restrict__ Alo,
    const __nv_bfloat16* __restrict__ Bhi, const __nv_bfloat16* __restrict__ Blo,
    float* __restrict__ out, const float* __restrict__ bias, int gemm_id) {
    extern __shared__ __nv_bfloat16 smT[];   // [2 buf][4 mat][128*LDT]
    __shared__ float sred[8][4];
    const int tid = threadIdx.x;
    const int lane = tid & 31;
    const int wid = tid >> 5;
    const int wm = wid >> 2;
    const int wn = wid & 3;
    const int m0 = blockIdx.y * 128;
    const int n0 = blockIdx.x * 128;
    const int qk = (gemm_id == 0 && blockIdx.y < 4);
    const int npass = qk ? 1 : 3;

    float acc[4][4][4];
#pragma unroll
    for (int i = 0; i < 4; i++)
#pragma unroll
        for (int j = 0; j < 4; j++)
#pragma unroll
            for (int r = 0; r < 4; r++) acc[i][j][r] = 0.f;

    const int lrow = tid >> 1;
    const int lch2 = (tid & 1) * 2;

#define TILE_BASE(buf, mat) (smT + ((buf) * 4 + (mat)) * (128 * LDT))
#define LOAD_STAGE(buf, kc)                                                             \
    do {                                                                                \
        const int k0 = (kc) * 32;                                                       \
        _Pragma("unroll")                                                               \
        for (int mat = 0; mat < 4; mat++) {                                             \
            if (npass == 1 && (mat == 1 || mat == 3)) continue;                         \
            const __nv_bfloat16* src =                                                  \
                ((mat == 0) ? Ahi : (mat == 1) ? Alo : (mat == 2) ? Bhi : Blo) +        \
                (size_t)(((mat < 2) ? m0 : n0) + lrow) * 256 + k0 + lch2 * 8;           \
            uint32_t d = smem_u32(TILE_BASE(buf, mat) + lrow * LDT + lch2 * 8);         \
            cp_async16(d, src);                                                         \
            cp_async16(d + 16, src + 8);                                                \
        }                                                                               \
        cp_commit();                                                                    \
    } while (0)

    LOAD_STAGE(0, 0);

    int buf = 0;
    for (int kc = 0; kc < 8; kc++) {
        if (kc + 1 < 8) {
            LOAD_STAGE(buf ^ 1, kc + 1);
            asm volatile("cp.async.wait_group 1;");
        } else {
            asm volatile("cp.async.wait_group 0;");
        }
        __syncthreads();

#pragma unroll 3
        for (int pass = 0; pass < npass; pass++) {
            const __nv_bfloat16* At = TILE_BASE(buf, (pass == 2) ? 1 : 0);
            const __nv_bfloat16* Bt = TILE_BASE(buf, (pass == 1) ? 3 : 2);
#pragma unroll
            for (int ks = 0; ks < 2; ks++) {
                uint32_t afr[4][4];
#pragma unroll
                for (int i = 0; i < 4; i++) {
                    uint32_t a = smem_u32(&At[(wm * 64 + i * 16 + (lane & 15)) * LDT +
                                             ((lane >> 4) * 8 + ks * 16)]);
                    ldsm_x4(afr[i], a);
                }
                uint32_t bfr[4][2];
#pragma unroll
                for (int j = 0; j < 4; j++) {
                    int l2 = lane & 15;
                    uint32_t a = smem_u32(&Bt[(wn * 32 + j * 8 + (l2 & 7)) * LDT +
                                             (((l2 >> 3) & 1) * 8 + ks * 16)]);
                    ldsm_x2(bfr[j], a);
                }
#pragma unroll
                for (int i = 0; i < 4; i++)
#pragma unroll
                    for (int j = 0; j < 4; j++) mma_bf16(acc[i][j], afr[i], bfr[j]);
            }
        }
        __syncthreads();
        buf ^= 1;
    }
#undef LOAD_STAGE
#undef TILE_BASE

    float s[2] = {0.f, 0.f}, s2[2] = {0.f, 0.f};
#pragma unroll
    for (int i = 0; i < 4; i++) {
        const int row = m0 + wm * 64 + i * 16 + (lane >> 2);
        const int gh = i >> 1;
        const float b0v = (gemm_id == 1) ? bias[row] : 0.f;
        const float b1v = (gemm_id == 1) ? bias[row + 8] : 0.f;
#pragma unroll
        for (int j = 0; j < 4; j++) {
            const int col = n0 + wn * 32 + j * 8 + (lane & 3) * 2;
            float v0x = acc[i][j][0] + b0v, v0y = acc[i][j][1] + b0v;
            float v1x = acc[i][j][2] + b1v, v1y = acc[i][j][3] + b1v;
            s[gh] += (v0x + v0y) + (v1x + v1y);
            s2[gh] += v0x * v0x + v0y * v0y + v1x * v1x + v1y * v1y;
            if (qk) {
                *(uint32_t*)(g_Yqk + (size_t)row * NTOK + col) = pack2bf(v0x, v0y);
                *(uint32_t*)(g_Yqk + (size_t)(row + 8) * NTOK + col) = pack2bf(v1x, v1y);
            } else if (gemm_id == 0) {
                float* vout = g_Yv + (size_t)(row - 512) * NTOK;
                *(float2*)(vout + col) = make_float2(v0x, v0y);
                *(float2*)(vout + (size_t)8 * NTOK + col) = make_float2(v1x, v1y);
            } else {
                *(float2*)(out + (size_t)row * NTOK + col) = make_float2(v0x, v0y);
                *(float2*)(out + (size_t)(row + 8) * NTOK + col) = make_float2(v1x, v1y);
            }
        }
    }

    int slot = (gemm_id == 0) ? (qk ? (int)(blockIdx.y >> 1) : -1) : 2;
    if (slot < 0) return;
    const int group_base = (gemm_id == 0) ? (blockIdx.y & 1) * 4 : blockIdx.y * 4;

#pragma unroll
    for (int off = 16; off > 0; off >>= 1) {
        s[0] += __shfl_xor_sync(0xffffffffu, s[0], off);
        s[1] += __shfl_xor_sync(0xffffffffu, s[1], off);
        s2[0] += __shfl_xor_sync(0xffffffffu, s2[0], off);
        s2[1] += __shfl_xor_sync(0xffffffffu, s2[1], off);
    }
    if (lane == 0) {
        sred[wid][0] = s[0]; sred[wid][1] = s[1];
        sred[wid][2] = s2[0]; sred[wid][3] = s2[1];
    }
    __syncthreads();
    if (tid < 4) {
        const int wmm = tid >> 1, gh = tid & 1;
        float ss = 0.f, ss2 = 0.f;
#pragma unroll
        for (int w = 0; w < 4; w++) {
            ss += sred[wmm * 4 + w][gh];
            ss2 += sred[wmm * 4 + w][2 + gh];
        }
        const int b = blockIdx.x >> 5;
        const int bxl = blockIdx.x & 31;
        const int pair = b * 8 + group_base + wmm * 2 + gh;
        g_part[slot][pair][bxl][0] = ss;
        g_part[slot][pair][bxl][1] = ss2;
    }
}

// ---------------- fused depthwise conv 3x3 + GeLU + conv 3x3 (R11 monolithic) --
__global__ __launch_bounds__(256) void dwconv_fused_kernel(
    const float* __restrict__ x,
    const float* __restrict__ dw1, const float* __restrict__ db1,
    const float* __restrict__ dw2, const float* __restrict__ db2) {
    __shared__ float xs[66 * 68];
    __shared__ float p1[66 * 68];
    const int bc = blockIdx.x;          // b*256 + c
    const int c = bc & 255;
    const float* xb = x + (size_t)bc * HWN;
    const int tid = threadIdx.x;

#pragma unroll
    for (int i = tid; i < 66 * 68; i += 256) { xs[i] = 0.f; p1[i] = 0.f; }
    float w1[9], w2[9];
#pragma unroll
    for (int i = 0; i < 9; i++) { w1[i] = dw1[c * 9 + i]; w2[i] = dw2[c * 9 + i]; }
    const float b1 = db1[c], b2 = db2[c];
    __syncthreads();

#pragma unroll
    for (int i = 0; i < 4; i++) {
        int idx = tid + i * 256;
        int py = idx >> 4, px4 = idx & 15;
        float4 v = *(const float4*)(xb + idx * 4);
        float* d = &xs[(py + 1) * 68 + 1 + px4 * 4];
        d[0] = v.x; d[1] = v.y; d[2] = v.z; d[3] = v.w;
    }
    __syncthreads();

#pragma unroll
    for (int i = 0; i < 4; i++) {
        int idx = tid + i * 256;              // pixel-group id
        int px4 = (idx & 15) * 4, py = idx >> 4;
        const float* base = &xs[py * 68 + px4];
        float r0[6], r1[6], r2[6];
        *(float4*)&r0[0] = *(const float4*)(base);
        *(float2*)&r0[4] = *(const float2*)(base + 4);
        *(float4*)&r1[0] = *(const float4*)(base + 68);
        *(float2*)&r1[4] = *(const float2*)(base + 72);
        *(float4*)&r2[0] = *(const float4*)(base + 136);
        *(float2*)&r2[4] = *(const float2*)(base + 140);
        float* prow = &p1[(py + 1) * 68 + px4 + 1];
#pragma unroll
        for (int p = 0; p < 4; p++) {
            float acc = b1;
            acc = fmaf(r0[p],     w1[0], acc);
            acc = fmaf(r0[p + 1], w1[1], acc);
            acc = fmaf(r0[p + 2], w1[2], acc);
            acc = fmaf(r1[p],     w1[3], acc);
            acc = fmaf(r1[p + 1], w1[4], acc);
            acc = fmaf(r1[p + 2], w1[5], acc);
            acc = fmaf(r2[p],     w1[6], acc);
            acc = fmaf(r2[p + 1], w1[7], acc);
            acc = fmaf(r2[p + 2], w1[8], acc);
            prow[p] = 0.5f * acc * (1.f + erff(acc * 0.70710678118654752f));
        }
    }
    __syncthreads();

#pragma unroll
    for (int i = 0; i < 4; i++) {
        int idx = tid + i * 256;
        int px4 = (idx & 15) * 4, py = idx >> 4;
        const float* base = &p1[py * 68 + px4];
        float r0[6], r1[6], r2[6];
        *(float4*)&r0[0] = *(const float4*)(base);
        *(float2*)&r0[4] = *(const float2*)(base + 4);
        *(float4*)&r1[0] = *(const float4*)(base + 68);
        *(float2*)&r1[4] = *(const float2*)(base + 72);
        *(float4*)&r2[0] = *(const float4*)(base + 136);
        *(float2*)&r2[4] = *(const float2*)(base + 140);
        float4 ov;
        float* po = &ov.x;
#pragma unroll
        for (int p = 0; p < 4; p++) {
            float acc = b2;
            acc = fmaf(r0[p],     w2[0], acc);
            acc = fmaf(r0[p + 1], w2[1], acc);
            acc = fmaf(r0[p + 2], w2[2], acc);
            acc = fmaf(r1[p],     w2[3], acc);
            acc = fmaf(r1[p + 1], w2[4], acc);
            acc = fmaf(r1[p + 2], w2[5], acc);
            acc = fmaf(r2[p],     w2[6], acc);
            acc = fmaf(r2[p + 1], w2[7], acc);
            acc = fmaf(r2[p + 2], w2[8], acc);
            po[p] = acc;
        }
        *(float4*)(g_pos + (size_t)bc * HWN + py * 64 + px4) = ov;
    }
}

// ---------------- attention: 16 tokens/block, bf16 q/k smem, single butterfly --
__global__ __launch_bounds__(512) void attn_kernel(
    const float* __restrict__ gqg, const float* __restrict__ gqb,
    const float* __restrict__ gkg, const float* __restrict__ gkb) {
    extern __shared__ char smraw[];
    unsigned short* smqk = (unsigned short*)smraw;           // [2][256*ATPB]
    float* smv = (float*)(smraw + 2 * 256 * ATPB * 2);       // [256*ATP]
    float* smp = smv + 256 * ATP;                            // [256*ATP]
    __shared__ float sstat[2][8][2];  // [slot q/k][head][mean,rstd]
    const int tid = threadIdx.x;
    const int warp = tid >> 5;        // 0..15 = token
    const int lane = tid & 31;
    const int n0 = blockIdx.x * 16;
    const int b = n0 >> 12;
    const int hw0 = n0 & 4095;

    if (warp < 16) {
        const int sl = warp >> 3;
        const int h = warp & 7;
        float s = g_part[sl][b * 8 + h][lane][0];
        float s2 = g_part[sl][b * 8 + h][lane][1];
#pragma unroll
        for (int off = 16; off > 0; off >>= 1) {
            s += __shfl_xor_sync(0xffffffffu, s, off);
            s2 += __shfl_xor_sync(0xffffffffu, s2, off);
        }
        if (lane == 0) {
            const float inv = 1.f / 131072.f;
            float mean = s * inv;
            float var = s2 * inv - mean * mean;
            sstat[sl][h][0] = mean;
            sstat[sl][h][1] = rsqrtf(var + EPS_GN);
        }
    }

    // q,k bf16 -> bf16 smem: 1024 slots of 8 bf16
#pragma unroll
    for (int r = 0; r < 2; r++) {
        int slot = tid + r * 512;
        int tens = slot >> 9;             // 0=q, 1=k
        int row = (slot >> 1) & 255;
        int half = (slot & 1) * 8;
        uint4 u = *(const uint4*)(g_Yqk + (size_t)(tens * 256 + row) * NTOK + n0 + half);
        uint32_t* d = (uint32_t*)(smqk + tens * (256 * ATPB) + row * ATPB + half);
        d[0] = u.x; d[1] = u.y; d[2] = u.z; d[3] = u.w;
    }
    // v fp32
#pragma unroll
    for (int r = 0; r < 2; r++) {
        int slot = tid + r * 512;
        int row = slot >> 2;
        int q4 = (slot & 3) * 4;
        float4 v = *(const float4*)(g_Yv + (size_t)row * NTOK + n0 + q4);
        float* dst = smv + row * ATP + q4;
        dst[0] = v.x; dst[1] = v.y; dst[2] = v.z; dst[3] = v.w;
    }
    // pos fp32 (NCHW)
#pragma unroll
    for (int r = 0; r < 2; r++) {
        int slot = tid + r * 512;
        int row = slot >> 2;
        int q4 = (slot & 3) * 4;
        float4 v = *(const float4*)(g_pos + (size_t)b * CHW + (size_t)row * HWN + hw0 + q4);
        float* dst = smp + row * ATP + q4;
        dst[0] = v.x; dst[1] = v.y; dst[2] = v.z; dst[3] = v.w;
    }
    __syncthreads();

    const float scale = 0.17677669529663687f;  // 1/sqrt(32)
    float oacc[8];
#pragma unroll 1
    for (int h = 0; h < 8; h++) {
        const int c = h * 32 + lane;
        float q = us2f(smqk[c * ATPB + warp]);
        float k = us2f(smqk[256 * ATPB + c * ATPB + warp]);
        float vv = smv[c * ATP + warp];
        q = (q - sstat[0][h][0]) * sstat[0][h][1] * gqg[c] + gqb[c];
        k = (k - sstat[1][h][0]) * sstat[1][h][1] * gkg[c] + gkb[c];

        const float k2 = k * k;
        const float k3 = k2 * k;
        const float k4 = k2 * k2;
        float sq = q * q;
        float m1 = k, m2 = k2, m3 = k3, m4 = k4;
        float w0 = vv, w1 = k * vv, w2 = k2 * vv, w3 = k3 * vv, w4 = k4 * vv;
#pragma unroll
        for (int off = 16; off > 0; off >>= 1) {
            sq += __shfl_xor_sync(0xffffffffu, sq, off);
            m1 += __shfl_xor_sync(0xffffffffu, m1, off);
            m2 += __shfl_xor_sync(0xffffffffu, m2, off);
            m3 += __shfl_xor_sync(0xffffffffu, m3, off);
            m4 += __shfl_xor_sync(0xffffffffu, m4, off);
            w0 += __shfl_xor_sync(0xffffffffu, w0, off);
            w1 += __shfl_xor_sync(0xffffffffu, w1, off);
            w2 += __shfl_xor_sync(0xffffffffu, w2, off);
            w3 += __shfl_xor_sync(0xffffffffu, w3, off);
            w4 += __shfl_xor_sync(0xffffffffu, w4, off);
        }
        const float rq = 1.f / fmaxf(sqrtf(sq), 1e-12f);
        const float rk = 1.f / fmaxf(sqrtf(m2), 1e-12f);
        const float rk2 = rk * rk, rk3 = rk2 * rk, rk4 = rk2 * rk2;
        const float s = q * rq * scale;

        const float c2 = 0.5f, c3 = 1.f / 6.f, c4 = 1.f / 24.f;
        const float a1 = m1 * rk, a2 = m2 * rk2, a3 = m3 * rk3, a4 = m4 * rk4;
        const float b1m = w1 * rk, b2 = w2 * rk2, b3 = w3 * rk3, b4 = w4 * rk4;
        float num = fmaf(s, fmaf(s, fmaf(s, fmaf(s, b4 * c4, b3 * c3), b2 * c2), b1m), w0);
        float den = fmaf(s, fmaf(s, fmaf(s, fmaf(s, a4 * c4, a3 * c3), a2 * c2), a1), 32.f);
        oacc[h] = __fdividef(num, den) + smp[c * ATP + warp];
    }
    // stage outputs into smv (each warp touches only its own token column)
#pragma unroll
    for (int h = 0; h < 8; h++) smv[(h * 32 + lane) * ATP + warp] = oacc[h];
    __syncthreads();

#pragma unroll
    for (int it = 0; it < 2; it++) {
        const int idx = tid + it * 512;
        const int j = idx >> 6;            // token 0..15
        const int c0 = (idx & 63) * 4;
        float f0 = smv[(c0 + 0) * ATP + j];
        float f1 = smv[(c0 + 1) * ATP + j];
        float f2 = smv[(c0 + 2) * ATP + j];
        float f3 = smv[(c0 + 3) * ATP + j];
        ushort4 hs, ls;
        hs.x = f2bf_us(f0); hs.y = f2bf_us(f1); hs.z = f2bf_us(f2); hs.w = f2bf_us(f3);
        ls.x = f2bf_us(f0 - __bfloat162float(__float2bfloat16(f0)));
        ls.y = f2bf_us(f1 - __bfloat162float(__float2bfloat16(f1)));
        ls.z = f2bf_us(f2 - __bfloat162float(__float2bfloat16(f2)));
        ls.w = f2bf_us(f3 - __bfloat162float(__float2bfloat16(f3)));
        const size_t n = (size_t)(n0 + j);
        *(ushort4*)(g_Uhi + n * 256 + c0) = hs;
        *(ushort4*)(g_Ulo + n * 256 + c0) = ls;
    }
}

// ---------------- final GN apply (stats reduced in-block) ----------------------
__global__ void gn_apply_kernel(const float* __restrict__ gamma,
                                const float* __restrict__ beta,
                                float* __restrict__ out) {
    __shared__ float sms[2];
    const int blk0 = blockIdx.x * 256;
    const int cB = blk0 >> 12;
    const int bB = ((blk0 & 4095) * 4) >> 12;
    if (threadIdx.x < 32) {
        const int lane = threadIdx.x;
        const int pair = bB * 8 + (cB >> 5);
        float s = g_part[2][pair][lane][0];
        float s2 = g_part[2][pair][lane][1];
#pragma unroll
        for (int off = 16; off > 0; off >>= 1) {
            s += __shfl_xor_sync(0xffffffffu, s, off);
            s2 += __shfl_xor_sync(0xffffffffu, s2, off);
        }
        if (lane == 0) {
            const float inv = 1.f / 131072.f;
            float mean = s * inv;
            float var = s2 * inv - mean * mean;
            sms[0] = mean;
            sms[1] = rsqrtf(var + EPS_GN);
        }
    }
    __syncthreads();
    const int idx4 = blk0 + threadIdx.x;
    const int c = idx4 >> 12;
    const int n = (idx4 & 4095) * 4;
    const int b = n >> 12;
    const float mean = sms[0], rstd = sms[1];
    const float ga = gamma[c], be = beta[c];
    float4 v = *(const float4*)(g_Z + (size_t)idx4 * 4);
    v.x = (v.x - mean) * rstd * ga + be;
    v.y = (v.y - mean) * rstd * ga + be;
    v.z = (v.z - mean) * rstd * ga + be;
    v.w = (v.w - mean) * rstd * ga + be;
    *(float4*)(out + (size_t)b * CHW + (size_t)c * HWN + (n & 4095)) = v;
}

// ---------------- launcher -----------------------------------------------------
extern "C" void kernel_launch(void* const* d_in, const int* in_sizes, int n_in,
                              void* d_out, int out_size) {
    const float* x        = (const float*)d_in[0];
    const float* wq       = (const float*)d_in[1];
    const float* gq_gamma = (const float*)d_in[2];
    const float* gq_beta  = (const float*)d_in[3];
    const float* wk       = (const float*)d_in[4];
    const float* gk_gamma = (const float*)d_in[5];
    const float* gk_beta  = (const float*)d_in[6];
    const float* wv       = (const float*)d_in[7];
    const float* wp       = (const float*)d_in[8];
    const float* bp       = (const float*)d_in[9];
    const float* gp_gamma = (const float*)d_in[10];
    const float* gp_beta  = (const float*)d_in[11];
    const float* dw1      = (const float*)d_in[12];
    const float* db1      = (const float*)d_in[13];
    const float* dw2      = (const float*)d_in[14];
    const float* db2      = (const float*)d_in[15];
    float* out = (float*)d_out;

    const int GEMM_SMEM = 2 * 4 * 128 * LDT * 2;            // 81920
    const int ATTN_SMEM = 2 * 256 * ATPB * 2 + 2 * 256 * ATP * 4;  // 18432 + 34816 = 53248
    static bool attr_set = false;
    if (!attr_set) {
        cudaFuncSetAttribute(attn_kernel, cudaFuncAttributeMaxDynamicSharedMemorySize, ATTN_SMEM);
        cudaFuncSetAttribute(mma_gemm_kernel, cudaFuncAttributeMaxDynamicSharedMemorySize, GEMM_SMEM);
        attr_set = true;
    }

    float *g_Z_p;
    __nv_bfloat16 *whi, *wlo, *wphi, *wplo, *xhi, *xlo, *uhi, *ulo;
    cudaGetSymbolAddress((void**)&g_Z_p, g_Z);
    cudaGetSymbolAddress((void**)&whi, g_Whi);
    cudaGetSymbolAddress((void**)&wlo, g_Wlo);
    cudaGetSymbolAddress((void**)&wphi, g_Wphi);
    cudaGetSymbolAddress((void**)&wplo, g_Wplo);
    cudaGetSymbolAddress((void**)&xhi, g_Xhi);
    cudaGetSymbolAddress((void**)&xlo, g_Xlo);
    cudaGetSymbolAddress((void**)&uhi, g_Uhi);
    cudaGetSymbolAddress((void**)&ulo, g_Ulo);

    // 1. weight + input conversion
    convert_w_kernel<<<1024, 256>>>(wq, wk, wv, wp);
    transpose_convert_kernel<<<dim3(128, 8, BATCH), 256>>>(x, HWN, CHW, xhi, xlo);
    // 2. QKV GEMM (q,k single-pass bf16 out; v 3-pass fp32; stats fused)
    mma_gemm_kernel<<<dim3(128, 6), 256, GEMM_SMEM>>>(whi, wlo, xhi, xlo, nullptr, nullptr, 0);
    // 3. fused positional path -> g_pos (monolithic, 1 block per plane)
    dwconv_fused_kernel<<<1024, 256>>>(x, dw1, db1, dw2, db2);
    // 4. attention (finalizes q/k stats in-block) + residual -> U bf16 hi/lo
    attn_kernel<<<1024, 512, ATTN_SMEM>>>(gq_gamma, gq_beta, gk_gamma, gk_beta);
    // 5. output projection GEMM (3-pass; z stats fused) -> g_Z [256][16384]
    mma_gemm_kernel<<<dim3(128, 2), 256, GEMM_SMEM>>>(wphi, wplo, uhi, ulo, g_Z_p, bp, 1);
    // 6. final group norm apply (finalizes z stats in-block)
    gn_apply_kernel<<<NTOK * 256 / 1024, 256>>>(gp_gamma, gp_beta, out);
}

// round 14
// speedup vs baseline: 1.0740x; 1.0450x over previous
#include <cuda_runtime.h>
#include <cuda_bf16.h>
#include <math.h>
#include <stdint.h>

#define BATCH 4
#define CCH 256
#define HWN 4096
#define NTOK 16384          // BATCH*HWN
#define CHW (CCH*HWN)
#define TOTAL (BATCH*CHW)
#define EPS_GN 1e-5f
#define LDT 40              // padded smem row length (bf16) for 32-wide K tile
#define NPART 32            // n-tiles per batch (4096/128)
#define ATP 17              // attn fp32 smem col pad (16 tokens + 1)
#define ATPB 18             // attn bf16 smem col pad (36-byte rows, conflict-free)

// ---------------- scratch (device globals) ------------------------------------
__device__ __nv_bfloat16 g_Yqk[(size_t)512 * NTOK];  // rows 0-255 q, 256-511 k (bf16)
__device__ float g_Yv[(size_t)256 * NTOK];           // v fp32 channel-major
__device__ float g_pos[TOTAL];                       // NCHW positional branch output
__device__ float g_Z[(size_t)CCH * NTOK];            // [256][16384] channel-major
__device__ float g_part[3][32][NPART][2];            // stats partials from GEMM epilogues
__device__ __nv_bfloat16 g_Whi[768 * 256], g_Wlo[768 * 256];
__device__ __nv_bfloat16 g_Wphi[256 * 256], g_Wplo[256 * 256];
__device__ __nv_bfloat16 g_Xhi[(size_t)NTOK * 256], g_Xlo[(size_t)NTOK * 256];
__device__ __nv_bfloat16 g_Uhi[(size_t)NTOK * 256], g_Ulo[(size_t)NTOK * 256];

// ---------------- helpers ------------------------------------------------------
__device__ __forceinline__ uint32_t smem_u32(const void* p) {
    return (uint32_t)__cvta_generic_to_shared(p);
}
__device__ __forceinline__ unsigned short f2bf_us(float v) {
    __nv_bfloat16 b = __float2bfloat16(v);
    return *reinterpret_cast<unsigned short*>(&b);
}
__device__ __forceinline__ float us2f(unsigned short u) {
    __nv_bfloat16 b = *reinterpret_cast<__nv_bfloat16*>(&u);
    return __bfloat162float(b);
}
__device__ __forceinline__ uint32_t pack2bf(float a, float b) {
    return ((uint32_t)f2bf_us(b) << 16) | f2bf_us(a);
}
__device__ __forceinline__ void cp_async16(uint32_t s, const void* g) {
    asm volatile("cp.async.cg.shared.global [%0], [%1], 16;" :: "r"(s), "l"(g));
}
__device__ __forceinline__ void cp_commit() {
    asm volatile("cp.async.commit_group;");
}
__device__ __forceinline__ void ldsm_x4(uint32_t* r, uint32_t a) {
    asm volatile("ldmatrix.sync.aligned.m8n8.x4.shared.b16 {%0,%1,%2,%3}, [%4];"
                 : "=r"(r[0]), "=r"(r[1]), "=r"(r[2]), "=r"(r[3]) : "r"(a));
}
__device__ __forceinline__ void ldsm_x2(uint32_t* r, uint32_t a) {
    asm volatile("ldmatrix.sync.aligned.m8n8.x2.shared.b16 {%0,%1}, [%2];"
                 : "=r"(r[0]), "=r"(r[1]) : "r"(a));
}
__device__ __forceinline__ void mma_bf16(float* c, const uint32_t* a, const uint32_t* b) {
    asm volatile(
        "mma.sync.aligned.m16n8k16.row.col.f32.bf16.bf16.f32 "
        "{%0,%1,%2,%3}, {%4,%5,%6,%7}, {%8,%9}, {%0,%1,%2,%3};"
        : "+f"(c[0]), "+f"(c[1]), "+f"(c[2]), "+f"(c[3])
        : "r"(a[0]), "r"(a[1]), "r"(a[2]), "r"(a[3]), "r"(b[0]), "r"(b[1]));
}

// ---------------- W -> bf16 hi/lo (K-major already) ---------------------------
__global__ void convert_w_kernel(const float* __restrict__ wq, const float* __restrict__ wk,
                                 const float* __restrict__ wv, const float* __restrict__ wp) {
    int i = blockIdx.x * 256 + threadIdx.x;  // 0..262143
    float v;
    __nv_bfloat16 *hi, *lo;
    int o;
    if (i < 65536)        { v = wq[i];          o = i;          hi = g_Whi;  lo = g_Wlo; }
    else if (i < 131072)  { v = wk[i - 65536];  o = i;          hi = g_Whi;  lo = g_Wlo; }
    else if (i < 196608)  { v = wv[i - 131072]; o = i;          hi = g_Whi;  lo = g_Wlo; }
    else                  { v = wp[i - 196608]; o = i - 196608; hi = g_Wphi; lo = g_Wplo; }
    __nv_bfloat16 h = __float2bfloat16(v);
    hi[o] = h;
    lo[o] = __float2bfloat16(v - __bfloat162float(h));
}

// ---------------- transpose [c][hw] fp32 -> token-major bf16 hi/lo -------------
__global__ void transpose_convert_kernel(const float* __restrict__ src, int c_stride, int b_stride,
                                         __nv_bfloat16* __restrict__ dhi,
                                         __nv_bfloat16* __restrict__ dlo) {
    __shared__ float t[32][33];
    const int hw0 = blockIdx.x * 32, c0 = blockIdx.y * 32, b = blockIdx.z;
    const int tid = threadIdx.x;
    const int rl = tid >> 3, q = tid & 7;
    float4 v = *(const float4*)(src + (size_t)b * b_stride + (size_t)(c0 + rl) * c_stride + hw0 + q * 4);
    t[rl][q * 4 + 0] = v.x; t[rl][q * 4 + 1] = v.y;
    t[rl][q * 4 + 2] = v.z; t[rl][q * 4 + 3] = v.w;
    __syncthreads();
    const int n = b * HWN + hw0 + rl;
    ushort4 hs, ls;
    float f0 = t[q * 4 + 0][rl], f1 = t[q * 4 + 1][rl];
    float f2 = t[q * 4 + 2][rl], f3 = t[q * 4 + 3][rl];
    hs.x = f2bf_us(f0); hs.y = f2bf_us(f1); hs.z = f2bf_us(f2); hs.w = f2bf_us(f3);
    ls.x = f2bf_us(f0 - __bfloat162float(__float2bfloat16(f0)));
    ls.y = f2bf_us(f1 - __bfloat162float(__float2bfloat16(f1)));
    ls.z = f2bf_us(f2 - __bfloat162float(__float2bfloat16(f2)));
    ls.w = f2bf_us(f3 - __bfloat162float(__float2bfloat16(f3)));
    *(ushort4*)(dhi + (size_t)n * 256 + c0 + q * 4) = hs;
    *(ushort4*)(dlo + (size_t)n * 256 + c0 + q * 4) = ls;
}

// ---------------- mma.sync GEMM + fused GN stats partials ----------------------
__global__ __launch_bounds__(256) void mma_gemm_kernel(
    const __nv_bfloat16* __restrict__ Ahi, const __nv_bfloat16* __restrict__ Alo,
    const __nv_bfloat16* __restrict__ Bhi, const __nv_bfloat16* __restrict__ Blo,
    float* __restrict__ out, const float* __restrict__ bias, int gemm_id) {
    extern __shared__ __nv_bfloat16 smT[];   // [2 buf][4 mat][128*LDT]
    __shared__ float sred[8][4];
    const int tid = threadIdx.x;
    const int lane = tid & 31;
    const int wid = tid >> 5;
    const int wm = wid >> 2;
    const int wn = wid & 3;
    const int m0 = blockIdx.y * 128;
    const int n0 = blockIdx.x * 128;
    const int qk = (gemm_id == 0 && blockIdx.y < 4);
    const int npass = qk ? 1 : 3;

    float acc[4][4][4];
#pragma unroll
    for (int i = 0; i < 4; i++)
#pragma unroll
        for (int j = 0; j < 4; j++)
#pragma unroll
            for (int r = 0; r < 4; r++) acc[i][j][r] = 0.f;

    const int lrow = tid >> 1;
    const int lch2 = (tid & 1) * 2;

#define TILE_BASE(buf, mat) (smT + ((buf) * 4 + (mat)) * (128 * LDT))
#define LOAD_STAGE(buf, kc)                                                             \
    do {                                                                                \
        const int k0 = (kc) * 32;                                                       \
        _Pragma("unroll")                                                               \
        for (int mat = 0; mat < 4; mat++) {                                             \
            if (npass == 1 && (mat == 1 || mat == 3)) continue;                         \
            const __nv_bfloat16* src =                                                  \
                ((mat == 0) ? Ahi : (mat == 1) ? Alo : (mat == 2) ? Bhi : Blo) +        \
                (size_t)(((mat < 2) ? m0 : n0) + lrow) * 256 + k0 + lch2 * 8;           \
            uint32_t d = smem_u32(TILE_BASE(buf, mat) + lrow * LDT + lch2 * 8);         \
            cp_async16(d, src);                                                         \
            cp_async16(d + 16, src + 8);                                                \
        }                                                                               \
        cp_commit();                                                                    \
    } while (0)

    LOAD_STAGE(0, 0);

    int buf = 0;
    for (int kc = 0; kc < 8; kc++) {
        if (kc + 1 < 8) {
            LOAD_STAGE(buf ^ 1, kc + 1);
            asm volatile("cp.async.wait_group 1;");
        } else {
            asm volatile("cp.async.wait_group 0;");
        }
        __syncthreads();

#pragma unroll 3
        for (int pass = 0; pass < npass; pass++) {
            const __nv_bfloat16* At = TILE_BASE(buf, (pass == 2) ? 1 : 0);
            const __nv_bfloat16* Bt = TILE_BASE(buf, (pass == 1) ? 3 : 2);
#pragma unroll
            for (int ks = 0; ks < 2; ks++) {
                uint32_t afr[4][4];
#pragma unroll
                for (int i = 0; i < 4; i++) {
                    uint32_t a = smem_u32(&At[(wm * 64 + i * 16 + (lane & 15)) * LDT +
                                             ((lane >> 4) * 8 + ks * 16)]);
                    ldsm_x4(afr[i], a);
                }
                uint32_t bfr[4][2];
#pragma unroll
                for (int j = 0; j < 4; j++) {
                    int l2 = lane & 15;
                    uint32_t a = smem_u32(&Bt[(wn * 32 + j * 8 + (l2 & 7)) * LDT +
                                             (((l2 >> 3) & 1) * 8 + ks * 16)]);
                    ldsm_x2(bfr[j], a);
                }
#pragma unroll
                for (int i = 0; i < 4; i++)
#pragma unroll
                    for (int j = 0; j < 4; j++) mma_bf16(acc[i][j], afr[i], bfr[j]);
            }
        }
        __syncthreads();
        buf ^= 1;
    }
#undef LOAD_STAGE
#undef TILE_BASE

    float s[2] = {0.f, 0.f}, s2[2] = {0.f, 0.f};
#pragma unroll
    for (int i = 0; i < 4; i++) {
        const int row = m0 + wm * 64 + i * 16 + (lane >> 2);
        const int gh = i >> 1;
        const float b0v = (gemm_id == 1) ? bias[row] : 0.f;
        const float b1v = (gemm_id == 1) ? bias[row + 8] : 0.f;
#pragma unroll
        for (int j = 0; j < 4; j++) {
            const int col = n0 + wn * 32 + j * 8 + (lane & 3) * 2;
            float v0x = acc[i][j][0] + b0v, v0y = acc[i][j][1] + b0v;
            float v1x = acc[i][j][2] + b1v, v1y = acc[i][j][3] + b1v;
            s[gh] += (v0x + v0y) + (v1x + v1y);
            s2[gh] += v0x * v0x + v0y * v0y + v1x * v1x + v1y * v1y;
            if (qk) {
                *(uint32_t*)(g_Yqk + (size_t)row * NTOK + col) = pack2bf(v0x, v0y);
                *(uint32_t*)(g_Yqk + (size_t)(row + 8) * NTOK + col) = pack2bf(v1x, v1y);
            } else if (gemm_id == 0) {
                float* vout = g_Yv + (size_t)(row - 512) * NTOK;
                *(float2*)(vout + col) = make_float2(v0x, v0y);
                *(float2*)(vout + (size_t)8 * NTOK + col) = make_float2(v1x, v1y);
            } else {
                *(float2*)(out + (size_t)row * NTOK + col) = make_float2(v0x, v0y);
                *(float2*)(out + (size_t)(row + 8) * NTOK + col) = make_float2(v1x, v1y);
            }
        }
    }

    int slot = (gemm_id == 0) ? (qk ? (int)(blockIdx.y >> 1) : -1) : 2;
    if (slot < 0) return;
    const int group_base = (gemm_id == 0) ? (blockIdx.y & 1) * 4 : blockIdx.y * 4;

#pragma unroll
    for (int off = 16; off > 0; off >>= 1) {
        s[0] += __shfl_xor_sync(0xffffffffu, s[0], off);
        s[1] += __shfl_xor_sync(0xffffffffu, s[1], off);
        s2[0] += __shfl_xor_sync(0xffffffffu, s2[0], off);
        s2[1] += __shfl_xor_sync(0xffffffffu, s2[1], off);
    }
    if (lane == 0) {
        sred[wid][0] = s[0]; sred[wid][1] = s[1];
        sred[wid][2] = s2[0]; sred[wid][3] = s2[1];
    }
    __syncthreads();
    if (tid < 4) {
        const int wmm = tid >> 1, gh = tid & 1;
        float ss = 0.f, ss2 = 0.f;
#pragma unroll
        for (int w = 0; w < 4; w++) {
            ss += sred[wmm * 4 + w][gh];
            ss2 += sred[wmm * 4 + w][2 + gh];
        }
        const int b = blockIdx.x >> 5;
        const int bxl = blockIdx.x & 31;
        const int pair = b * 8 + group_base + wmm * 2 + gh;
        g_part[slot][pair][bxl][0] = ss;
        g_part[slot][pair][bxl][1] = ss2;
    }
}

// ---------------- fused dwconv 3x3 + GeLU + conv 3x3: 4x4 patch/thread ---------
__global__ __launch_bounds__(256) void dwconv_fused_kernel(
    const float* __restrict__ x,
    const float* __restrict__ dw1, const float* __restrict__ db1,
    const float* __restrict__ dw2, const float* __restrict__ db2) {
    __shared__ float xs[66 * 68];
    __shared__ float p1[66 * 68];
    const int bc = blockIdx.x;          // b*256 + c
    const int c = bc & 255;
    const float* xb = x + (size_t)bc * HWN;
    const int tid = threadIdx.x;
    const int tx4 = (tid & 15) * 4;     // output px base
    const int ty4 = (tid >> 4) * 4;     // output row base

#pragma unroll
    for (int i = tid; i < 66 * 68; i += 256) { xs[i] = 0.f; p1[i] = 0.f; }
    float w1[9], w2[9];
#pragma unroll
    for (int i = 0; i < 9; i++) { w1[i] = dw1[c * 9 + i]; w2[i] = dw2[c * 9 + i]; }
    const float b1 = db1[c], b2 = db2[c];
    __syncthreads();

#pragma unroll
    for (int i = 0; i < 4; i++) {
        int idx = tid + i * 256;
        int py = idx >> 4, px4 = idx & 15;
        float4 v = *(const float4*)(xb + idx * 4);
        float* d = &xs[(py + 1) * 68 + 1 + px4 * 4];
        d[0] = v.x; d[1] = v.y; d[2] = v.z; d[3] = v.w;
    }
    __syncthreads();

    // phase 1: each thread computes p1 rows ty4..ty4+3 x cols tx4..tx4+3
    {
        float r[6][6];
#pragma unroll
        for (int rr = 0; rr < 6; rr++) {
            const float* base = &xs[(ty4 + rr) * 68 + tx4];
            *(float4*)&r[rr][0] = *(const float4*)(base);
            *(float2*)&r[rr][4] = *(const float2*)(base + 4);
        }
#pragma unroll
        for (int orow = 0; orow < 4; orow++) {
            float* prow = &p1[(ty4 + orow + 1) * 68 + tx4 + 1];
#pragma unroll
            for (int p = 0; p < 4; p++) {
                float acc = b1;
                acc = fmaf(r[orow][p],         w1[0], acc);
                acc = fmaf(r[orow][p + 1],     w1[1], acc);
                acc = fmaf(r[orow][p + 2],     w1[2], acc);
                acc = fmaf(r[orow + 1][p],     w1[3], acc);
                acc = fmaf(r[orow + 1][p + 1], w1[4], acc);
                acc = fmaf(r[orow + 1][p + 2], w1[5], acc);
                acc = fmaf(r[orow + 2][p],     w1[6], acc);
                acc = fmaf(r[orow + 2][p + 1], w1[7], acc);
                acc = fmaf(r[orow + 2][p + 2], w1[8], acc);
                prow[p] = 0.5f * acc * (1.f + erff(acc * 0.70710678118654752f));
            }
        }
    }
    __syncthreads();

    // phase 2: output rows ty4..ty4+3 x cols tx4..tx4+3
    {
        float r[6][6];
#pragma unroll
        for (int rr = 0; rr < 6; rr++) {
            const float* base = &p1[(ty4 + rr) * 68 + tx4];
            *(float4*)&r[rr][0] = *(const float4*)(base);
            *(float2*)&r[rr][4] = *(const float2*)(base + 4);
        }
#pragma unroll
        for (int orow = 0; orow < 4; orow++) {
            float4 ov;
            float* po = &ov.x;
#pragma unroll
            for (int p = 0; p < 4; p++) {
                float acc = b2;
                acc = fmaf(r[orow][p],         w2[0], acc);
                acc = fmaf(r[orow][p + 1],     w2[1], acc);
                acc = fmaf(r[orow][p + 2],     w2[2], acc);
                acc = fmaf(r[orow + 1][p],     w2[3], acc);
                acc = fmaf(r[orow + 1][p + 1], w2[4], acc);
                acc = fmaf(r[orow + 1][p + 2], w2[5], acc);
                acc = fmaf(r[orow + 2][p],     w2[6], acc);
                acc = fmaf(r[orow + 2][p + 1], w2[7], acc);
                acc = fmaf(r[orow + 2][p + 2], w2[8], acc);
                po[p] = acc;
            }
            *(float4*)(g_pos + (size_t)bc * HWN + (ty4 + orow) * 64 + tx4) = ov;
        }
    }
}

// ---------------- attention: 16 tokens/block, bf16 q/k smem, single butterfly --
__global__ __launch_bounds__(512) void attn_kernel(
    const float* __restrict__ gqg, const float* __restrict__ gqb,
    const float* __restrict__ gkg, const float* __restrict__ gkb) {
    extern __shared__ char smraw[];
    unsigned short* smqk = (unsigned short*)smraw;           // [2][256*ATPB]
    float* smv = (float*)(smraw + 2 * 256 * ATPB * 2);       // [256*ATP]
    float* smp = smv + 256 * ATP;                            // [256*ATP]
    __shared__ float sstat[2][8][2];  // [slot q/k][head][mean,rstd]
    const int tid = threadIdx.x;
    const int warp = tid >> 5;        // 0..15 = token
    const int lane = tid & 31;
    const int n0 = blockIdx.x * 16;
    const int b = n0 >> 12;
    const int hw0 = n0 & 4095;

    if (warp < 16) {
        const int sl = warp >> 3;
        const int h = warp & 7;
        float s = g_part[sl][b * 8 + h][lane][0];
        float s2 = g_part[sl][b * 8 + h][lane][1];
#pragma unroll
        for (int off = 16; off > 0; off >>= 1) {
            s += __shfl_xor_sync(0xffffffffu, s, off);
            s2 += __shfl_xor_sync(0xffffffffu, s2, off);
        }
        if (lane == 0) {
            const float inv = 1.f / 131072.f;
            float mean = s * inv;
            float var = s2 * inv - mean * mean;
            sstat[sl][h][0] = mean;
            sstat[sl][h][1] = rsqrtf(var + EPS_GN);
        }
    }

#pragma unroll
    for (int r = 0; r < 2; r++) {
        int slot = tid + r * 512;
        int tens = slot >> 9;             // 0=q, 1=k
        int row = (slot >> 1) & 255;
        int half = (slot & 1) * 8;
        uint4 u = *(const uint4*)(g_Yqk + (size_t)(tens * 256 + row) * NTOK + n0 + half);
        uint32_t* d = (uint32_t*)(smqk + tens * (256 * ATPB) + row * ATPB + half);
        d[0] = u.x; d[1] = u.y; d[2] = u.z; d[3] = u.w;
    }
#pragma unroll
    for (int r = 0; r < 2; r++) {
        int slot = tid + r * 512;
        int row = slot >> 2;
        int q4 = (slot & 3) * 4;
        float4 v = *(const float4*)(g_Yv + (size_t)row * NTOK + n0 + q4);
        float* dst = smv + row * ATP + q4;
        dst[0] = v.x; dst[1] = v.y; dst[2] = v.z; dst[3] = v.w;
    }
#pragma unroll
    for (int r = 0; r < 2; r++) {
        int slot = tid + r * 512;
        int row = slot >> 2;
        int q4 = (slot & 3) * 4;
        float4 v = *(const float4*)(g_pos + (size_t)b * CHW + (size_t)row * HWN + hw0 + q4);
        float* dst = smp + row * ATP + q4;
        dst[0] = v.x; dst[1] = v.y; dst[2] = v.z; dst[3] = v.w;
    }
    __syncthreads();

    const float scale = 0.17677669529663687f;  // 1/sqrt(32)
    float oacc[8];
#pragma unroll 1
    for (int h = 0; h < 8; h++) {
        const int c = h * 32 + lane;
        float q = us2f(smqk[c * ATPB + warp]);
        float k = us2f(smqk[256 * ATPB + c * ATPB + warp]);
        float vv = smv[c * ATP + warp];
        q = (q - sstat[0][h][0]) * sstat[0][h][1] * gqg[c] + gqb[c];
        k = (k - sstat[1][h][0]) * sstat[1][h][1] * gkg[c] + gkb[c];

        const float k2 = k * k;
        const float k3 = k2 * k;
        const float k4 = k2 * k2;
        float sq = q * q;
        float m1 = k, m2 = k2, m3 = k3, m4 = k4;
        float w0 = vv, w1 = k * vv, w2 = k2 * vv, w3 = k3 * vv, w4 = k4 * vv;
#pragma unroll
        for (int off = 16; off > 0; off >>= 1) {
            sq += __shfl_xor_sync(0xffffffffu, sq, off);
            m1 += __shfl_xor_sync(0xffffffffu, m1, off);
            m2 += __shfl_xor_sync(0xffffffffu, m2, off);
            m3 += __shfl_xor_sync(0xffffffffu, m3, off);
            m4 += __shfl_xor_sync(0xffffffffu, m4, off);
            w0 += __shfl_xor_sync(0xffffffffu, w0, off);
            w1 += __shfl_xor_sync(0xffffffffu, w1, off);
            w2 += __shfl_xor_sync(0xffffffffu, w2, off);
            w3 += __shfl_xor_sync(0xffffffffu, w3, off);
            w4 += __shfl_xor_sync(0xffffffffu, w4, off);
        }
        const float rq = 1.f / fmaxf(sqrtf(sq), 1e-12f);
        const float rk = 1.f / fmaxf(sqrtf(m2), 1e-12f);
        const float rk2 = rk * rk, rk3 = rk2 * rk, rk4 = rk2 * rk2;
        const float s = q * rq * scale;

        const float c2 = 0.5f, c3 = 1.f / 6.f, c4 = 1.f / 24.f;
        const float a1 = m1 * rk, a2 = m2 * rk2, a3 = m3 * rk3, a4 = m4 * rk4;
        const float b1m = w1 * rk, b2 = w2 * rk2, b3 = w3 * rk3, b4 = w4 * rk4;
        float num = fmaf(s, fmaf(s, fmaf(s, fmaf(s, b4 * c4, b3 * c3), b2 * c2), b1m), w0);
        float den = fmaf(s, fmaf(s, fmaf(s, fmaf(s, a4 * c4, a3 * c3), a2 * c2), a1), 32.f);
        oacc[h] = __fdividef(num, den) + smp[c * ATP + warp];
    }
#pragma unroll
    for (int h = 0; h < 8; h++) smv[(h * 32 + lane) * ATP + warp] = oacc[h];
    __syncthreads();

#pragma unroll
    for (int it = 0; it < 2; it++) {
        const int idx = tid + it * 512;
        const int j = idx >> 6;            // token 0..15
        const int c0 = (idx & 63) * 4;
        float f0 = smv[(c0 + 0) * ATP + j];
        float f1 = smv[(c0 + 1) * ATP + j];
        float f2 = smv[(c0 + 2) * ATP + j];
        float f3 = smv[(c0 + 3) * ATP + j];
        ushort4 hs, ls;
        hs.x = f2bf_us(f0); hs.y = f2bf_us(f1); hs.z = f2bf_us(f2); hs.w = f2bf_us(f3);
        ls.x = f2bf_us(f0 - __bfloat162float(__float2bfloat16(f0)));
        ls.y = f2bf_us(f1 - __bfloat162float(__float2bfloat16(f1)));
        ls.z = f2bf_us(f2 - __bfloat162float(__float2bfloat16(f2)));
        ls.w = f2bf_us(f3 - __bfloat162float(__float2bfloat16(f3)));
        const size_t n = (size_t)(n0 + j);
        *(ushort4*)(g_Uhi + n * 256 + c0) = hs;
        *(ushort4*)(g_Ulo + n * 256 + c0) = ls;
    }
}

// ---------------- final GN apply (stats reduced in-block) ----------------------
__global__ void gn_apply_kernel(const float* __restrict__ gamma,
                                const float* __restrict__ beta,
                                float* __restrict__ out) {
    __shared__ float sms[2];
    const int blk0 = blockIdx.x * 256;
    const int cB = blk0 >> 12;
    const int bB = ((blk0 & 4095) * 4) >> 12;
    if (threadIdx.x < 32) {
        const int lane = threadIdx.x;
        const int pair = bB * 8 + (cB >> 5);
        float s = g_part[2][pair][lane][0];
        float s2 = g_part[2][pair][lane][1];
#pragma unroll
        for (int off = 16; off > 0; off >>= 1) {
            s += __shfl_xor_sync(0xffffffffu, s, off);
            s2 += __shfl_xor_sync(0xffffffffu, s2, off);
        }
        if (lane == 0) {
            const float inv = 1.f / 131072.f;
            float mean = s * inv;
            float var = s2 * inv - mean * mean;
            sms[0] = mean;
            sms[1] = rsqrtf(var + EPS_GN);
        }
    }
    __syncthreads();
    const int idx4 = blk0 + threadIdx.x;
    const int c = idx4 >> 12;
    const int n = (idx4 & 4095) * 4;
    const int b = n >> 12;
    const float mean = sms[0], rstd = sms[1];
    const float ga = gamma[c], be = beta[c];
    float4 v = *(const float4*)(g_Z + (size_t)idx4 * 4);
    v.x = (v.x - mean) * rstd * ga + be;
    v.y = (v.y - mean) * rstd * ga + be;
    v.z = (v.z - mean) * rstd * ga + be;
    v.w = (v.w - mean) * rstd * ga + be;
    *(float4*)(out + (size_t)b * CHW + (size_t)c * HWN + (n & 4095)) = v;
}

// ---------------- launcher -----------------------------------------------------
extern "C" void kernel_launch(void* const* d_in, const int* in_sizes, int n_in,
                              void* d_out, int out_size) {
    const float* x        = (const float*)d_in[0];
    const float* wq       = (const float*)d_in[1];
    const float* gq_gamma = (const float*)d_in[2];
    const float* gq_beta  = (const float*)d_in[3];
    const float* wk       = (const float*)d_in[4];
    const float* gk_gamma = (const float*)d_in[5];
    const float* gk_beta  = (const float*)d_in[6];
    const float* wv       = (const float*)d_in[7];
    const float* wp       = (const float*)d_in[8];
    const float* bp       = (const float*)d_in[9];
    const float* gp_gamma = (const float*)d_in[10];
    const float* gp_beta  = (const float*)d_in[11];
    const float* dw1      = (const float*)d_in[12];
    const float* db1      = (const float*)d_in[13];
    const float* dw2      = (const float*)d_in[14];
    const float* db2      = (const float*)d_in[15];
    float* out = (float*)d_out;

    const int GEMM_SMEM = 2 * 4 * 128 * LDT * 2;                   // 81920
    const int ATTN_SMEM = 2 * 256 * ATPB * 2 + 2 * 256 * ATP * 4;  // 53248

    static cudaStream_t s1;
    static cudaEvent_t evStart, evW, evD;
    static bool init_done = false;
    if (!init_done) {
        cudaFuncSetAttribute(attn_kernel, cudaFuncAttributeMaxDynamicSharedMemorySize, ATTN_SMEM);
        cudaFuncSetAttribute(mma_gemm_kernel, cudaFuncAttributeMaxDynamicSharedMemorySize, GEMM_SMEM);
        cudaStreamCreateWithFlags(&s1, cudaStreamNonBlocking);
        cudaEventCreateWithFlags(&evStart, cudaEventDisableTiming);
        cudaEventCreateWithFlags(&evW, cudaEventDisableTiming);
        cudaEventCreateWithFlags(&evD, cudaEventDisableTiming);
        init_done = true;
    }

    float *g_Z_p;
    __nv_bfloat16 *whi, *wlo, *wphi, *wplo, *xhi, *xlo, *uhi, *ulo;
    cudaGetSymbolAddress((void**)&g_Z_p, g_Z);
    cudaGetSymbolAddress((void**)&whi, g_Whi);
    cudaGetSymbolAddress((void**)&wlo, g_Wlo);
    cudaGetSymbolAddress((void**)&wphi, g_Wphi);
    cudaGetSymbolAddress((void**)&wplo, g_Wplo);
    cudaGetSymbolAddress((void**)&xhi, g_Xhi);
    cudaGetSymbolAddress((void**)&xlo, g_Xlo);
    cudaGetSymbolAddress((void**)&uhi, g_Uhi);
    cudaGetSymbolAddress((void**)&ulo, g_Ulo);

    // fork side stream s1 off main stream
    cudaEventRecord(evStart, 0);
    cudaStreamWaitEvent(s1, evStart, 0);

    // s1: weight conversion (feeds GEMM1), then independent dwconv path
    convert_w_kernel<<<1024, 256, 0, s1>>>(wq, wk, wv, wp);
    cudaEventRecord(evW, s1);
    dwconv_fused_kernel<<<1024, 256, 0, s1>>>(x, dw1, db1, dw2, db2);
    cudaEventRecord(evD, s1);

    // s0: transpose (independent of weights), then GEMM1 after weights ready
    transpose_convert_kernel<<<dim3(128, 8, BATCH), 256>>>(x, HWN, CHW, xhi, xlo);
    cudaStreamWaitEvent(0, evW, 0);
    mma_gemm_kernel<<<dim3(128, 6), 256, GEMM_SMEM>>>(whi, wlo, xhi, xlo, nullptr, nullptr, 0);
    // attn needs dwconv output
    cudaStreamWaitEvent(0, evD, 0);
    attn_kernel<<<1024, 512, ATTN_SMEM>>>(gq_gamma, gq_beta, gk_gamma, gk_beta);
    mma_gemm_kernel<<<dim3(128, 2), 256, GEMM_SMEM>>>(wphi, wplo, uhi, ulo, g_Z_p, bp, 1);
    gn_apply_kernel<<<NTOK * 256 / 1024, 256>>>(gp_gamma, gp_beta, out);
}

// round 15
// speedup vs baseline: 1.0805x; 1.0061x over previous
#include <cuda_runtime.h>
#include <cuda_bf16.h>
#include <math.h>
#include <stdint.h>

#define BATCH 4
#define CCH 256
#define HWN 4096
#define NTOK 16384          // BATCH*HWN
#define CHW (CCH*HWN)
#define TOTAL (BATCH*CHW)
#define EPS_GN 1e-5f
#define LDT 40              // padded smem row length (bf16) for 32-wide K tile
#define NPART 32            // n-tiles per batch (4096/128)
#define ATP 17              // attn fp32 smem col pad (16 tokens + 1)
#define ATPB 18             // attn bf16 smem col pad

// ---------------- scratch (device globals) ------------------------------------
__device__ __nv_bfloat16 g_Yqk[(size_t)512 * NTOK];  // rows 0-255 q, 256-511 k (bf16)
__device__ float g_Yv[(size_t)256 * NTOK];           // v fp32 channel-major
__device__ float g_pos[TOTAL];                       // NCHW positional branch output
__device__ float g_Z[(size_t)CCH * NTOK];            // [256][16384] channel-major
__device__ float g_part[3][32][NPART][2];            // stats partials from GEMM epilogues
__device__ __nv_bfloat16 g_Whi[768 * 256], g_Wlo[768 * 256];
__device__ __nv_bfloat16 g_Wphi[256 * 256], g_Wplo[256 * 256];
__device__ __nv_bfloat16 g_Xhi[(size_t)NTOK * 256], g_Xlo[(size_t)NTOK * 256];
__device__ __nv_bfloat16 g_Uhi[(size_t)NTOK * 256], g_Ulo[(size_t)NTOK * 256];

// ---------------- helpers ------------------------------------------------------
__device__ __forceinline__ uint32_t smem_u32(const void* p) {
    return (uint32_t)__cvta_generic_to_shared(p);
}
__device__ __forceinline__ unsigned short f2bf_us(float v) {
    __nv_bfloat16 b = __float2bfloat16(v);
    return *reinterpret_cast<unsigned short*>(&b);
}
__device__ __forceinline__ float us2f(unsigned short u) {
    __nv_bfloat16 b = *reinterpret_cast<__nv_bfloat16*>(&u);
    return __bfloat162float(b);
}
__device__ __forceinline__ uint32_t pack2bf(float a, float b) {
    return ((uint32_t)f2bf_us(b) << 16) | f2bf_us(a);
}
__device__ __forceinline__ void cp_async16(uint32_t s, const void* g) {
    asm volatile("cp.async.cg.shared.global [%0], [%1], 16;" :: "r"(s), "l"(g));
}
__device__ __forceinline__ void cp_commit() {
    asm volatile("cp.async.commit_group;");
}
__device__ __forceinline__ void ldsm_x4(uint32_t* r, uint32_t a) {
    asm volatile("ldmatrix.sync.aligned.m8n8.x4.shared.b16 {%0,%1,%2,%3}, [%4];"
                 : "=r"(r[0]), "=r"(r[1]), "=r"(r[2]), "=r"(r[3]) : "r"(a));
}
__device__ __forceinline__ void ldsm_x2(uint32_t* r, uint32_t a) {
    asm volatile("ldmatrix.sync.aligned.m8n8.x2.shared.b16 {%0,%1}, [%2];"
                 : "=r"(r[0]), "=r"(r[1]) : "r"(a));
}
__device__ __forceinline__ void mma_bf16(float* c, const uint32_t* a, const uint32_t* b) {
    asm volatile(
        "mma.sync.aligned.m16n8k16.row.col.f32.bf16.bf16.f32 "
        "{%0,%1,%2,%3}, {%4,%5,%6,%7}, {%8,%9}, {%0,%1,%2,%3};"
        : "+f"(c[0]), "+f"(c[1]), "+f"(c[2]), "+f"(c[3])
        : "r"(a[0]), "r"(a[1]), "r"(a[2]), "r"(a[3]), "r"(b[0]), "r"(b[1]));
}

// ---------------- W -> bf16 hi/lo (K-major already) ---------------------------
__global__ void convert_w_kernel(const float* __restrict__ wq, const float* __restrict__ wk,
                                 const float* __restrict__ wv, const float* __restrict__ wp) {
    int i = blockIdx.x * 256 + threadIdx.x;  // 0..262143
    float v;
    __nv_bfloat16 *hi, *lo;
    int o;
    if (i < 65536)        { v = wq[i];          o = i;          hi = g_Whi;  lo = g_Wlo; }
    else if (i < 131072)  { v = wk[i - 65536];  o = i;          hi = g_Whi;  lo = g_Wlo; }
    else if (i < 196608)  { v = wv[i - 131072]; o = i;          hi = g_Whi;  lo = g_Wlo; }
    else                  { v = wp[i - 196608]; o = i - 196608; hi = g_Wphi; lo = g_Wplo; }
    __nv_bfloat16 h = __float2bfloat16(v);
    hi[o] = h;
    lo[o] = __float2bfloat16(v - __bfloat162float(h));
}

// ---------------- transpose [c][hw] fp32 -> token-major bf16 hi/lo -------------
__global__ void transpose_convert_kernel(const float* __restrict__ src, int c_stride, int b_stride,
                                         __nv_bfloat16* __restrict__ dhi,
                                         __nv_bfloat16* __restrict__ dlo) {
    __shared__ float t[32][33];
    const int hw0 = blockIdx.x * 32, c0 = blockIdx.y * 32, b = blockIdx.z;
    const int tid = threadIdx.x;
    const int rl = tid >> 3, q = tid & 7;
    float4 v = *(const float4*)(src + (size_t)b * b_stride + (size_t)(c0 + rl) * c_stride + hw0 + q * 4);
    t[rl][q * 4 + 0] = v.x; t[rl][q * 4 + 1] = v.y;
    t[rl][q * 4 + 2] = v.z; t[rl][q * 4 + 3] = v.w;
    __syncthreads();
    const int n = b * HWN + hw0 + rl;
    ushort4 hs, ls;
    float f0 = t[q * 4 + 0][rl], f1 = t[q * 4 + 1][rl];
    float f2 = t[q * 4 + 2][rl], f3 = t[q * 4 + 3][rl];
    hs.x = f2bf_us(f0); hs.y = f2bf_us(f1); hs.z = f2bf_us(f2); hs.w = f2bf_us(f3);
    ls.x = f2bf_us(f0 - __bfloat162float(__float2bfloat16(f0)));
    ls.y = f2bf_us(f1 - __bfloat162float(__float2bfloat16(f1)));
    ls.z = f2bf_us(f2 - __bfloat162float(__float2bfloat16(f2)));
    ls.w = f2bf_us(f3 - __bfloat162float(__float2bfloat16(f3)));
    *(ushort4*)(dhi + (size_t)n * 256 + c0 + q * 4) = hs;
    *(ushort4*)(dlo + (size_t)n * 256 + c0 + q * 4) = ls;
}

// ---------------- mma.sync GEMM, 16 warps x 32x32 warp tile --------------------
// gemm1 q,k blocks (y<4): single bf16 pass -> g_Yqk (bf16).
// gemm1 v blocks (y=4,5): 3-pass split -> g_Yv (fp32).
// gemm2: 3-pass split -> out (+bias).
__global__ __launch_bounds__(512, 2) void mma_gemm_kernel(
    const __nv_bfloat16* __restrict__ Ahi, const __nv_bfloat16* __restrict__ Alo,
    const __nv_bfloat16* __restrict__ Bhi, const __nv_bfloat16* __restrict__ Blo,
    float* __restrict__ out, const float* __restrict__ bias, int gemm_id) {
    extern __shared__ __nv_bfloat16 smT[];   // [2 buf][4 mat][128*LDT]
    __shared__ float sred[16][2];
    const int tid = threadIdx.x;
    const int lane = tid & 31;
    const int wid = tid >> 5;         // 0..15
    const int wm = wid >> 2;          // 0..3 (32 rows each)
    const int wn = wid & 3;           // 0..3 (32 cols each)
    const int m0 = blockIdx.y * 128;
    const int n0 = blockIdx.x * 128;
    const int qk = (gemm_id == 0 && blockIdx.y < 4);
    const int npass = qk ? 1 : 3;

    float acc[2][4][4];
#pragma unroll
    for (int i = 0; i < 2; i++)
#pragma unroll
        for (int j = 0; j < 4; j++)
#pragma unroll
            for (int r = 0; r < 4; r++) acc[i][j][r] = 0.f;

    const int lrow = tid >> 2;            // 0..127
    const int lch = tid & 3;              // 16B chunk 0..3

#define TILE_BASE(buf, mat) (smT + ((buf) * 4 + (mat)) * (128 * LDT))
#define LOAD_STAGE(buf, kc)                                                             \
    do {                                                                                \
        const int k0 = (kc) * 32;                                                       \
        _Pragma("unroll")                                                               \
        for (int mat = 0; mat < 4; mat++) {                                             \
            if (npass == 1 && (mat == 1 || mat == 3)) continue;                         \
            const __nv_bfloat16* src =                                                  \
                ((mat == 0) ? Ahi : (mat == 1) ? Alo : (mat == 2) ? Bhi : Blo) +        \
                (size_t)(((mat < 2) ? m0 : n0) + lrow) * 256 + k0 + lch * 8;            \
            cp_async16(smem_u32(TILE_BASE(buf, mat) + lrow * LDT + lch * 8), src);      \
        }                                                                               \
        cp_commit();                                                                    \
    } while (0)

    LOAD_STAGE(0, 0);

    int buf = 0;
    for (int kc = 0; kc < 8; kc++) {
        if (kc + 1 < 8) {
            LOAD_STAGE(buf ^ 1, kc + 1);
            asm volatile("cp.async.wait_group 1;");
        } else {
            asm volatile("cp.async.wait_group 0;");
        }
        __syncthreads();

#pragma unroll 3
        for (int pass = 0; pass < npass; pass++) {
            const __nv_bfloat16* At = TILE_BASE(buf, (pass == 2) ? 1 : 0);
            const __nv_bfloat16* Bt = TILE_BASE(buf, (pass == 1) ? 3 : 2);
#pragma unroll
            for (int ks = 0; ks < 2; ks++) {
                uint32_t afr[2][4];
#pragma unroll
                for (int i = 0; i < 2; i++) {
                    uint32_t a = smem_u32(&At[(wm * 32 + i * 16 + (lane & 15)) * LDT +
                                             ((lane >> 4) * 8 + ks * 16)]);
                    ldsm_x4(afr[i], a);
                }
                uint32_t bfr[4][2];
#pragma unroll
                for (int j = 0; j < 4; j++) {
                    int l2 = lane & 15;
                    uint32_t a = smem_u32(&Bt[(wn * 32 + j * 8 + (l2 & 7)) * LDT +
                                             (((l2 >> 3) & 1) * 8 + ks * 16)]);
                    ldsm_x2(bfr[j], a);
                }
#pragma unroll
                for (int i = 0; i < 2; i++)
#pragma unroll
                    for (int j = 0; j < 4; j++) mma_bf16(acc[i][j], afr[i], bfr[j]);
            }
        }
        __syncthreads();
        buf ^= 1;
    }
#undef LOAD_STAGE
#undef TILE_BASE

    // epilogue: stores + per-warp GN stats (warp's 32 rows = one group g=wm)
    float s = 0.f, s2 = 0.f;
#pragma unroll
    for (int i = 0; i < 2; i++) {
        const int row = m0 + wm * 32 + i * 16 + (lane >> 2);
        const float b0v = (gemm_id == 1) ? bias[row] : 0.f;
        const float b1v = (gemm_id == 1) ? bias[row + 8] : 0.f;
#pragma unroll
        for (int j = 0; j < 4; j++) {
            const int col = n0 + wn * 32 + j * 8 + (lane & 3) * 2;
            float v0x = acc[i][j][0] + b0v, v0y = acc[i][j][1] + b0v;
            float v1x = acc[i][j][2] + b1v, v1y = acc[i][j][3] + b1v;
            s += (v0x + v0y) + (v1x + v1y);
            s2 += v0x * v0x + v0y * v0y + v1x * v1x + v1y * v1y;
            if (qk) {
                *(uint32_t*)(g_Yqk + (size_t)row * NTOK + col) = pack2bf(v0x, v0y);
                *(uint32_t*)(g_Yqk + (size_t)(row + 8) * NTOK + col) = pack2bf(v1x, v1y);
            } else if (gemm_id == 0) {
                float* vout = g_Yv + (size_t)(row - 512) * NTOK;
                *(float2*)(vout + col) = make_float2(v0x, v0y);
                *(float2*)(vout + (size_t)8 * NTOK + col) = make_float2(v1x, v1y);
            } else {
                *(float2*)(out + (size_t)row * NTOK + col) = make_float2(v0x, v0y);
                *(float2*)(out + (size_t)(row + 8) * NTOK + col) = make_float2(v1x, v1y);
            }
        }
    }

    int slot = (gemm_id == 0) ? (qk ? (int)(blockIdx.y >> 1) : -1) : 2;
    if (slot < 0) return;
    const int group_base = (gemm_id == 0) ? (blockIdx.y & 1) * 4 : blockIdx.y * 4;

#pragma unroll
    for (int off = 16; off > 0; off >>= 1) {
        s += __shfl_xor_sync(0xffffffffu, s, off);
        s2 += __shfl_xor_sync(0xffffffffu, s2, off);
    }
    if (lane == 0) { sred[wid][0] = s; sred[wid][1] = s2; }
    __syncthreads();
    if (tid < 4) {
        const int g = tid;
        float ss = 0.f, ss2 = 0.f;
#pragma unroll
        for (int w = 0; w < 4; w++) {
            ss += sred[g * 4 + w][0];
            ss2 += sred[g * 4 + w][1];
        }
        const int b = blockIdx.x >> 5;
        const int bxl = blockIdx.x & 31;
        const int pair = b * 8 + group_base + g;
        g_part[slot][pair][bxl][0] = ss;
        g_part[slot][pair][bxl][1] = ss2;
    }
}

// ---------------- fused dwconv 3x3 + GeLU + conv 3x3: 4x4 patch/thread ---------
__global__ __launch_bounds__(256) void dwconv_fused_kernel(
    const float* __restrict__ x,
    const float* __restrict__ dw1, const float* __restrict__ db1,
    const float* __restrict__ dw2, const float* __restrict__ db2) {
    __shared__ float xs[66 * 68];
    __shared__ float p1[66 * 68];
    const int bc = blockIdx.x;          // b*256 + c
    const int c = bc & 255;
    const float* xb = x + (size_t)bc * HWN;
    const int tid = threadIdx.x;
    const int tx4 = (tid & 15) * 4;
    const int ty4 = (tid >> 4) * 4;

#pragma unroll
    for (int i = tid; i < 66 * 68; i += 256) { xs[i] = 0.f; p1[i] = 0.f; }
    float w1[9], w2[9];
#pragma unroll
    for (int i = 0; i < 9; i++) { w1[i] = dw1[c * 9 + i]; w2[i] = dw2[c * 9 + i]; }
    const float b1 = db1[c], b2 = db2[c];
    __syncthreads();

#pragma unroll
    for (int i = 0; i < 4; i++) {
        int idx = tid + i * 256;
        int py = idx >> 4, px4 = idx & 15;
        float4 v = *(const float4*)(xb + idx * 4);
        float* d = &xs[(py + 1) * 68 + 1 + px4 * 4];
        d[0] = v.x; d[1] = v.y; d[2] = v.z; d[3] = v.w;
    }
    __syncthreads();

    {
        float r[6][6];
#pragma unroll
        for (int rr = 0; rr < 6; rr++) {
            const float* base = &xs[(ty4 + rr) * 68 + tx4];
            *(float4*)&r[rr][0] = *(const float4*)(base);
            *(float2*)&r[rr][4] = *(const float2*)(base + 4);
        }
#pragma unroll
        for (int orow = 0; orow < 4; orow++) {
            float* prow = &p1[(ty4 + orow + 1) * 68 + tx4 + 1];
#pragma unroll
            for (int p = 0; p < 4; p++) {
                float acc = b1;
                acc = fmaf(r[orow][p],         w1[0], acc);
                acc = fmaf(r[orow][p + 1],     w1[1], acc);
                acc = fmaf(r[orow][p + 2],     w1[2], acc);
                acc = fmaf(r[orow + 1][p],     w1[3], acc);
                acc = fmaf(r[orow + 1][p + 1], w1[4], acc);
                acc = fmaf(r[orow + 1][p + 2], w1[5], acc);
                acc = fmaf(r[orow + 2][p],     w1[6], acc);
                acc = fmaf(r[orow + 2][p + 1], w1[7], acc);
                acc = fmaf(r[orow + 2][p + 2], w1[8], acc);
                prow[p] = 0.5f * acc * (1.f + erff(acc * 0.70710678118654752f));
            }
        }
    }
    __syncthreads();

    {
        float r[6][6];
#pragma unroll
        for (int rr = 0; rr < 6; rr++) {
            const float* base = &p1[(ty4 + rr) * 68 + tx4];
            *(float4*)&r[rr][0] = *(const float4*)(base);
            *(float2*)&r[rr][4] = *(const float2*)(base + 4);
        }
#pragma unroll
        for (int orow = 0; orow < 4; orow++) {
            float4 ov;
            float* po = &ov.x;
#pragma unroll
            for (int p = 0; p < 4; p++) {
                float acc = b2;
                acc = fmaf(r[orow][p],         w2[0], acc);
                acc = fmaf(r[orow][p + 1],     w2[1], acc);
                acc = fmaf(r[orow][p + 2],     w2[2], acc);
                acc = fmaf(r[orow + 1][p],     w2[3], acc);
                acc = fmaf(r[orow + 1][p + 1], w2[4], acc);
                acc = fmaf(r[orow + 1][p + 2], w2[5], acc);
                acc = fmaf(r[orow + 2][p],     w2[6], acc);
                acc = fmaf(r[orow + 2][p + 1], w2[7], acc);
                acc = fmaf(r[orow + 2][p + 2], w2[8], acc);
                po[p] = acc;
            }
            *(float4*)(g_pos + (size_t)bc * HWN + (ty4 + orow) * 64 + tx4) = ov;
        }
    }
}

// ---------------- attention: 16 tokens/block, bf16 q/k smem, single butterfly --
__global__ __launch_bounds__(512) void attn_kernel(
    const float* __restrict__ gqg, const float* __restrict__ gqb,
    const float* __restrict__ gkg, const float* __restrict__ gkb) {
    extern __shared__ char smraw[];
    unsigned short* smqk = (unsigned short*)smraw;           // [2][256*ATPB]
    float* smv = (float*)(smraw + 2 * 256 * ATPB * 2);       // [256*ATP]
    float* smp = smv + 256 * ATP;                            // [256*ATP]
    __shared__ float sstat[2][8][2];
    const int tid = threadIdx.x;
    const int warp = tid >> 5;        // 0..15 = token
    const int lane = tid & 31;
    const int n0 = blockIdx.x * 16;
    const int b = n0 >> 12;
    const int hw0 = n0 & 4095;

    if (warp < 16) {
        const int sl = warp >> 3;
        const int h = warp & 7;
        float s = g_part[sl][b * 8 + h][lane][0];
        float s2 = g_part[sl][b * 8 + h][lane][1];
#pragma unroll
        for (int off = 16; off > 0; off >>= 1) {
            s += __shfl_xor_sync(0xffffffffu, s, off);
            s2 += __shfl_xor_sync(0xffffffffu, s2, off);
        }
        if (lane == 0) {
            const float inv = 1.f / 131072.f;
            float mean = s * inv;
            float var = s2 * inv - mean * mean;
            sstat[sl][h][0] = mean;
            sstat[sl][h][1] = rsqrtf(var + EPS_GN);
        }
    }

#pragma unroll
    for (int r = 0; r < 2; r++) {
        int slot = tid + r * 512;
        int tens = slot >> 9;
        int row = (slot >> 1) & 255;
        int half = (slot & 1) * 8;
        uint4 u = *(const uint4*)(g_Yqk + (size_t)(tens * 256 + row) * NTOK + n0 + half);
        uint32_t* d = (uint32_t*)(smqk + tens * (256 * ATPB) + row * ATPB + half);
        d[0] = u.x; d[1] = u.y; d[2] = u.z; d[3] = u.w;
    }
#pragma unroll
    for (int r = 0; r < 2; r++) {
        int slot = tid + r * 512;
        int row = slot >> 2;
        int q4 = (slot & 3) * 4;
        float4 v = *(const float4*)(g_Yv + (size_t)row * NTOK + n0 + q4);
        float* dst = smv + row * ATP + q4;
        dst[0] = v.x; dst[1] = v.y; dst[2] = v.z; dst[3] = v.w;
    }
#pragma unroll
    for (int r = 0; r < 2; r++) {
        int slot = tid + r * 512;
        int row = slot >> 2;
        int q4 = (slot & 3) * 4;
        float4 v = *(const float4*)(g_pos + (size_t)b * CHW + (size_t)row * HWN + hw0 + q4);
        float* dst = smp + row * ATP + q4;
        dst[0] = v.x; dst[1] = v.y; dst[2] = v.z; dst[3] = v.w;
    }
    __syncthreads();

    const float scale = 0.17677669529663687f;  // 1/sqrt(32)
    float oacc[8];
#pragma unroll 1
    for (int h = 0; h < 8; h++) {
        const int c = h * 32 + lane;
        float q = us2f(smqk[c * ATPB + warp]);
        float k = us2f(smqk[256 * ATPB + c * ATPB + warp]);
        float vv = smv[c * ATP + warp];
        q = (q - sstat[0][h][0]) * sstat[0][h][1] * gqg[c] + gqb[c];
        k = (k - sstat[1][h][0]) * sstat[1][h][1] * gkg[c] + gkb[c];

        const float k2 = k * k;
        const float k3 = k2 * k;
        const float k4 = k2 * k2;
        float sq = q * q;
        float m1 = k, m2 = k2, m3 = k3, m4 = k4;
        float w0 = vv, w1 = k * vv, w2 = k2 * vv, w3 = k3 * vv, w4 = k4 * vv;
#pragma unroll
        for (int off = 16; off > 0; off >>= 1) {
            sq += __shfl_xor_sync(0xffffffffu, sq, off);
            m1 += __shfl_xor_sync(0xffffffffu, m1, off);
            m2 += __shfl_xor_sync(0xffffffffu, m2, off);
            m3 += __shfl_xor_sync(0xffffffffu, m3, off);
            m4 += __shfl_xor_sync(0xffffffffu, m4, off);
            w0 += __shfl_xor_sync(0xffffffffu, w0, off);
            w1 += __shfl_xor_sync(0xffffffffu, w1, off);
            w2 += __shfl_xor_sync(0xffffffffu, w2, off);
            w3 += __shfl_xor_sync(0xffffffffu, w3, off);
            w4 += __shfl_xor_sync(0xffffffffu, w4, off);
        }
        const float rq = 1.f / fmaxf(sqrtf(sq), 1e-12f);
        const float rk = 1.f / fmaxf(sqrtf(m2), 1e-12f);
        const float rk2 = rk * rk, rk3 = rk2 * rk, rk4 = rk2 * rk2;
        const float s = q * rq * scale;

        const float c2 = 0.5f, c3 = 1.f / 6.f, c4 = 1.f / 24.f;
        const float a1 = m1 * rk, a2 = m2 * rk2, a3 = m3 * rk3, a4 = m4 * rk4;
        const float b1m = w1 * rk, b2 = w2 * rk2, b3 = w3 * rk3, b4 = w4 * rk4;
        float num = fmaf(s, fmaf(s, fmaf(s, fmaf(s, b4 * c4, b3 * c3), b2 * c2), b1m), w0);
        float den = fmaf(s, fmaf(s, fmaf(s, fmaf(s, a4 * c4, a3 * c3), a2 * c2), a1), 32.f);
        oacc[h] = __fdividef(num, den) + smp[c * ATP + warp];
    }
#pragma unroll
    for (int h = 0; h < 8; h++) smv[(h * 32 + lane) * ATP + warp] = oacc[h];
    __syncthreads();

#pragma unroll
    for (int it = 0; it < 2; it++) {
        const int idx = tid + it * 512;
        const int j = idx >> 6;
        const int c0 = (idx & 63) * 4;
        float f0 = smv[(c0 + 0) * ATP + j];
        float f1 = smv[(c0 + 1) * ATP + j];
        float f2 = smv[(c0 + 2) * ATP + j];
        float f3 = smv[(c0 + 3) * ATP + j];
        ushort4 hs, ls;
        hs.x = f2bf_us(f0); hs.y = f2bf_us(f1); hs.z = f2bf_us(f2); hs.w = f2bf_us(f3);
        ls.x = f2bf_us(f0 - __bfloat162float(__float2bfloat16(f0)));
        ls.y = f2bf_us(f1 - __bfloat162float(__float2bfloat16(f1)));
        ls.z = f2bf_us(f2 - __bfloat162float(__float2bfloat16(f2)));
        ls.w = f2bf_us(f3 - __bfloat162float(__float2bfloat16(f3)));
        const size_t n = (size_t)(n0 + j);
        *(ushort4*)(g_Uhi + n * 256 + c0) = hs;
        *(ushort4*)(g_Ulo + n * 256 + c0) = ls;
    }
}

// ---------------- final GN apply (stats reduced in-block) ----------------------
__global__ void gn_apply_kernel(const float* __restrict__ gamma,
                                const float* __restrict__ beta,
                                float* __restrict__ out) {
    __shared__ float sms[2];
    const int blk0 = blockIdx.x * 256;
    const int cB = blk0 >> 12;
    const int bB = ((blk0 & 4095) * 4) >> 12;
    if (threadIdx.x < 32) {
        const int lane = threadIdx.x;
        const int pair = bB * 8 + (cB >> 5);
        float s = g_part[2][pair][lane][0];
        float s2 = g_part[2][pair][lane][1];
#pragma unroll
        for (int off = 16; off > 0; off >>= 1) {
            s += __shfl_xor_sync(0xffffffffu, s, off);
            s2 += __shfl_xor_sync(0xffffffffu, s2, off);
        }
        if (lane == 0) {
            const float inv = 1.f / 131072.f;
            float mean = s * inv;
            float var = s2 * inv - mean * mean;
            sms[0] = mean;
            sms[1] = rsqrtf(var + EPS_GN);
        }
    }
    __syncthreads();
    const int idx4 = blk0 + threadIdx.x;
    const int c = idx4 >> 12;
    const int n = (idx4 & 4095) * 4;
    const int b = n >> 12;
    const float mean = sms[0], rstd = sms[1];
    const float ga = gamma[c], be = beta[c];
    float4 v = *(const float4*)(g_Z + (size_t)idx4 * 4);
    v.x = (v.x - mean) * rstd * ga + be;
    v.y = (v.y - mean) * rstd * ga + be;
    v.z = (v.z - mean) * rstd * ga + be;
    v.w = (v.w - mean) * rstd * ga + be;
    *(float4*)(out + (size_t)b * CHW + (size_t)c * HWN + (n & 4095)) = v;
}

// ---------------- launcher -----------------------------------------------------
extern "C" void kernel_launch(void* const* d_in, const int* in_sizes, int n_in,
                              void* d_out, int out_size) {
    const float* x        = (const float*)d_in[0];
    const float* wq       = (const float*)d_in[1];
    const float* gq_gamma = (const float*)d_in[2];
    const float* gq_beta  = (const float*)d_in[3];
    const float* wk       = (const float*)d_in[4];
    const float* gk_gamma = (const float*)d_in[5];
    const float* gk_beta  = (const float*)d_in[6];
    const float* wv       = (const float*)d_in[7];
    const float* wp       = (const float*)d_in[8];
    const float* bp       = (const float*)d_in[9];
    const float* gp_gamma = (const float*)d_in[10];
    const float* gp_beta  = (const float*)d_in[11];
    const float* dw1      = (const float*)d_in[12];
    const float* db1      = (const float*)d_in[13];
    const float* dw2      = (const float*)d_in[14];
    const float* db2      = (const float*)d_in[15];
    float* out = (float*)d_out;

    const int GEMM_SMEM = 2 * 4 * 128 * LDT * 2;                   // 81920
    const int ATTN_SMEM = 2 * 256 * ATPB * 2 + 2 * 256 * ATP * 4;  // 53248

    static cudaStream_t s1;
    static cudaEvent_t evStart, evW, evD;
    static bool init_done = false;
    if (!init_done) {
        cudaFuncSetAttribute(attn_kernel, cudaFuncAttributeMaxDynamicSharedMemorySize, ATTN_SMEM);
        cudaFuncSetAttribute(mma_gemm_kernel, cudaFuncAttributeMaxDynamicSharedMemorySize, GEMM_SMEM);
        cudaStreamCreateWithFlags(&s1, cudaStreamNonBlocking);
        cudaEventCreateWithFlags(&evStart, cudaEventDisableTiming);
        cudaEventCreateWithFlags(&evW, cudaEventDisableTiming);
        cudaEventCreateWithFlags(&evD, cudaEventDisableTiming);
        init_done = true;
    }

    float *g_Z_p;
    __nv_bfloat16 *whi, *wlo, *wphi, *wplo, *xhi, *xlo, *uhi, *ulo;
    cudaGetSymbolAddress((void**)&g_Z_p, g_Z);
    cudaGetSymbolAddress((void**)&whi, g_Whi);
    cudaGetSymbolAddress((void**)&wlo, g_Wlo);
    cudaGetSymbolAddress((void**)&wphi, g_Wphi);
    cudaGetSymbolAddress((void**)&wplo, g_Wplo);
    cudaGetSymbolAddress((void**)&xhi, g_Xhi);
    cudaGetSymbolAddress((void**)&xlo, g_Xlo);
    cudaGetSymbolAddress((void**)&uhi, g_Uhi);
    cudaGetSymbolAddress((void**)&ulo, g_Ulo);

    // fork side stream s1 off main stream
    cudaEventRecord(evStart, 0);
    cudaStreamWaitEvent(s1, evStart, 0);

    // s1: weight conversion (feeds GEMM1), then independent dwconv path
    convert_w_kernel<<<1024, 256, 0, s1>>>(wq, wk, wv, wp);
    cudaEventRecord(evW, s1);
    dwconv_fused_kernel<<<1024, 256, 0, s1>>>(x, dw1, db1, dw2, db2);
    cudaEventRecord(evD, s1);

    // s0: transpose (independent of weights), then GEMM1 after weights ready
    transpose_convert_kernel<<<dim3(128, 8, BATCH), 256>>>(x, HWN, CHW, xhi, xlo);
    cudaStreamWaitEvent(0, evW, 0);
    mma_gemm_kernel<<<dim3(128, 6), 512, GEMM_SMEM>>>(whi, wlo, xhi, xlo, nullptr, nullptr, 0);
    // attn needs dwconv output
    cudaStreamWaitEvent(0, evD, 0);
    attn_kernel<<<1024, 512, ATTN_SMEM>>>(gq_gamma, gq_beta, gk_gamma, gk_beta);
    mma_gemm_kernel<<<dim3(128, 2), 512, GEMM_SMEM>>>(wphi, wplo, uhi, ulo, g_Z_p, bp, 1);
    gn_apply_kernel<<<NTOK * 256 / 1024, 256>>>(gp_gamma, gp_beta, out);
}

// round 16
// speedup vs baseline: 1.1494x; 1.0638x over previous
#include <cuda_runtime.h>
#include <cuda_bf16.h>
#include <math.h>
#include <stdint.h>

#define BATCH 4
#define CCH 256
#define HWN 4096
#define NTOK 16384          // BATCH*HWN
#define CHW (CCH*HWN)
#define TOTAL (BATCH*CHW)
#define EPS_GN 1e-5f
#define LDT 40              // padded smem row length (bf16) for 32-wide K tile
#define NPART 32            // n-tiles per batch (4096/128)
#define ATP 17              // attn fp32 smem col pad (16 tokens + 1)
#define ATPB 18             // attn bf16 smem col pad

// ---------------- scratch (device globals) ------------------------------------
__device__ __nv_bfloat16 g_Yqk[(size_t)512 * NTOK];  // rows 0-255 q, 256-511 k (bf16)
__device__ float g_Yv[(size_t)256 * NTOK];           // v fp32 channel-major
__device__ float g_pos[TOTAL];                       // NCHW positional branch output
__device__ float g_Z[(size_t)CCH * NTOK];            // [256][16384] channel-major
__device__ float g_part[3][32][NPART][2];            // stats partials from GEMM epilogues
__device__ __nv_bfloat16 g_Whi[768 * 256], g_Wlo[768 * 256];
__device__ __nv_bfloat16 g_Wphi[256 * 256], g_Wplo[256 * 256];
__device__ __nv_bfloat16 g_Xhi[(size_t)NTOK * 256], g_Xlo[(size_t)NTOK * 256];
__device__ __nv_bfloat16 g_Uhi[(size_t)NTOK * 256], g_Ulo[(size_t)NTOK * 256];

// ---------------- helpers ------------------------------------------------------
__device__ __forceinline__ uint32_t smem_u32(const void* p) {
    return (uint32_t)__cvta_generic_to_shared(p);
}
__device__ __forceinline__ unsigned short f2bf_us(float v) {
    __nv_bfloat16 b = __float2bfloat16(v);
    return *reinterpret_cast<unsigned short*>(&b);
}
__device__ __forceinline__ float us2f(unsigned short u) {
    __nv_bfloat16 b = *reinterpret_cast<__nv_bfloat16*>(&u);
    return __bfloat162float(b);
}
__device__ __forceinline__ uint32_t pack2bf(float a, float b) {
    return ((uint32_t)f2bf_us(b) << 16) | f2bf_us(a);
}
__device__ __forceinline__ void cp_async16(uint32_t s, const void* g) {
    asm volatile("cp.async.cg.shared.global [%0], [%1], 16;" :: "r"(s), "l"(g));
}
__device__ __forceinline__ void cp_commit() {
    asm volatile("cp.async.commit_group;");
}
__device__ __forceinline__ void ldsm_x4(uint32_t* r, uint32_t a) {
    asm volatile("ldmatrix.sync.aligned.m8n8.x4.shared.b16 {%0,%1,%2,%3}, [%4];"
                 : "=r"(r[0]), "=r"(r[1]), "=r"(r[2]), "=r"(r[3]) : "r"(a));
}
__device__ __forceinline__ void mma_bf16(float* c, const uint32_t* a, const uint32_t* b) {
    asm volatile(
        "mma.sync.aligned.m16n8k16.row.col.f32.bf16.bf16.f32 "
        "{%0,%1,%2,%3}, {%4,%5,%6,%7}, {%8,%9}, {%0,%1,%2,%3};"
        : "+f"(c[0]), "+f"(c[1]), "+f"(c[2]), "+f"(c[3])
        : "r"(a[0]), "r"(a[1]), "r"(a[2]), "r"(a[3]), "r"(b[0]), "r"(b[1]));
}

// ---------------- W -> bf16 hi/lo (K-major already) ---------------------------
__global__ void convert_w_kernel(const float* __restrict__ wq, const float* __restrict__ wk,
                                 const float* __restrict__ wv, const float* __restrict__ wp) {
    int i = blockIdx.x * 256 + threadIdx.x;  // 0..262143
    float v;
    __nv_bfloat16 *hi, *lo;
    int o;
    if (i < 65536)        { v = wq[i];          o = i;          hi = g_Whi;  lo = g_Wlo; }
    else if (i < 131072)  { v = wk[i - 65536];  o = i;          hi = g_Whi;  lo = g_Wlo; }
    else if (i < 196608)  { v = wv[i - 131072]; o = i;          hi = g_Whi;  lo = g_Wlo; }
    else                  { v = wp[i - 196608]; o = i - 196608; hi = g_Wphi; lo = g_Wplo; }
    __nv_bfloat16 h = __float2bfloat16(v);
    hi[o] = h;
    lo[o] = __float2bfloat16(v - __bfloat162float(h));
}

// ---------------- transpose [c][hw] fp32 -> token-major bf16 hi/lo -------------
__global__ void transpose_convert_kernel(const float* __restrict__ src, int c_stride, int b_stride,
                                         __nv_bfloat16* __restrict__ dhi,
                                         __nv_bfloat16* __restrict__ dlo) {
    __shared__ float t[32][33];
    const int hw0 = blockIdx.x * 32, c0 = blockIdx.y * 32, b = blockIdx.z;
    const int tid = threadIdx.x;
    const int rl = tid >> 3, q = tid & 7;
    float4 v = *(const float4*)(src + (size_t)b * b_stride + (size_t)(c0 + rl) * c_stride + hw0 + q * 4);
    t[rl][q * 4 + 0] = v.x; t[rl][q * 4 + 1] = v.y;
    t[rl][q * 4 + 2] = v.z; t[rl][q * 4 + 3] = v.w;
    __syncthreads();
    const int n = b * HWN + hw0 + rl;
    ushort4 hs, ls;
    float f0 = t[q * 4 + 0][rl], f1 = t[q * 4 + 1][rl];
    float f2 = t[q * 4 + 2][rl], f3 = t[q * 4 + 3][rl];
    hs.x = f2bf_us(f0); hs.y = f2bf_us(f1); hs.z = f2bf_us(f2); hs.w = f2bf_us(f3);
    ls.x = f2bf_us(f0 - __bfloat162float(__float2bfloat16(f0)));
    ls.y = f2bf_us(f1 - __bfloat162float(__float2bfloat16(f1)));
    ls.z = f2bf_us(f2 - __bfloat162float(__float2bfloat16(f2)));
    ls.w = f2bf_us(f3 - __bfloat162float(__float2bfloat16(f3)));
    *(ushort4*)(dhi + (size_t)n * 256 + c0 + q * 4) = hs;
    *(ushort4*)(dlo + (size_t)n * 256 + c0 + q * 4) = ls;
}

// ---------------- mma.sync GEMM, 16 warps x 32x32 warp tile --------------------
// B fragments loaded 2-at-a-time via ldsm_x4 (lanes 16-31 address 2nd tile).
__global__ __launch_bounds__(512, 2) void mma_gemm_kernel(
    const __nv_bfloat16* __restrict__ Ahi, const __nv_bfloat16* __restrict__ Alo,
    const __nv_bfloat16* __restrict__ Bhi, const __nv_bfloat16* __restrict__ Blo,
    float* __restrict__ out, const float* __restrict__ bias, int gemm_id) {
    extern __shared__ __nv_bfloat16 smT[];   // [2 buf][4 mat][128*LDT]
    __shared__ float sred[16][2];
    const int tid = threadIdx.x;
    const int lane = tid & 31;
    const int wid = tid >> 5;         // 0..15
    const int wm = wid >> 2;          // 0..3 (32 rows each)
    const int wn = wid & 3;           // 0..3 (32 cols each)
    const int m0 = blockIdx.y * 128;
    const int n0 = blockIdx.x * 128;
    const int qk = (gemm_id == 0 && blockIdx.y < 4);
    const int npass = qk ? 1 : 3;

    float acc[2][4][4];
#pragma unroll
    for (int i = 0; i < 2; i++)
#pragma unroll
        for (int j = 0; j < 4; j++)
#pragma unroll
            for (int r = 0; r < 4; r++) acc[i][j][r] = 0.f;

    const int lrow = tid >> 2;            // 0..127
    const int lch = tid & 3;              // 16B chunk 0..3

#define TILE_BASE(buf, mat) (smT + ((buf) * 4 + (mat)) * (128 * LDT))
#define LOAD_STAGE(buf, kc)                                                             \
    do {                                                                                \
        const int k0 = (kc) * 32;                                                       \
        _Pragma("unroll")                                                               \
        for (int mat = 0; mat < 4; mat++) {                                             \
            if (npass == 1 && (mat == 1 || mat == 3)) continue;                         \
            const __nv_bfloat16* src =                                                  \
                ((mat == 0) ? Ahi : (mat == 1) ? Alo : (mat == 2) ? Bhi : Blo) +        \
                (size_t)(((mat < 2) ? m0 : n0) + lrow) * 256 + k0 + lch * 8;            \
            cp_async16(smem_u32(TILE_BASE(buf, mat) + lrow * LDT + lch * 8), src);      \
        }                                                                               \
        cp_commit();                                                                    \
    } while (0)

    LOAD_STAGE(0, 0);

    int buf = 0;
    for (int kc = 0; kc < 8; kc++) {
        if (kc + 1 < 8) {
            LOAD_STAGE(buf ^ 1, kc + 1);
            asm volatile("cp.async.wait_group 1;");
        } else {
            asm volatile("cp.async.wait_group 0;");
        }
        __syncthreads();

#pragma unroll 3
        for (int pass = 0; pass < npass; pass++) {
            const __nv_bfloat16* At = TILE_BASE(buf, (pass == 2) ? 1 : 0);
            const __nv_bfloat16* Bt = TILE_BASE(buf, (pass == 1) ? 3 : 2);
#pragma unroll
            for (int ks = 0; ks < 2; ks++) {
                uint32_t afr[2][4];
#pragma unroll
                for (int i = 0; i < 2; i++) {
                    uint32_t a = smem_u32(&At[(wm * 32 + i * 16 + (lane & 15)) * LDT +
                                             ((lane >> 4) * 8 + ks * 16)]);
                    ldsm_x4(afr[i], a);
                }
                // B: two ldsm_x4, each covering j-pair (2 fragments)
                uint32_t bfr[4][2];
#pragma unroll
                for (int jp = 0; jp < 2; jp++) {
                    uint32_t a = smem_u32(&Bt[(wn * 32 + (jp * 2 + ((lane >> 4) & 1)) * 8 +
                                              (lane & 7)) * LDT +
                                             (((lane >> 3) & 1) * 8 + ks * 16)]);
                    uint32_t r[4];
                    ldsm_x4(r, a);
                    bfr[jp * 2][0] = r[0]; bfr[jp * 2][1] = r[1];
                    bfr[jp * 2 + 1][0] = r[2]; bfr[jp * 2 + 1][1] = r[3];
                }
#pragma unroll
                for (int i = 0; i < 2; i++)
#pragma unroll
                    for (int j = 0; j < 4; j++) mma_bf16(acc[i][j], afr[i], bfr[j]);
            }
        }
        __syncthreads();
        buf ^= 1;
    }
#undef LOAD_STAGE
#undef TILE_BASE

    // epilogue: stores + per-warp GN stats (warp's 32 rows = one group g=wm)
    float s = 0.f, s2 = 0.f;
#pragma unroll
    for (int i = 0; i < 2; i++) {
        const int row = m0 + wm * 32 + i * 16 + (lane >> 2);
        const float b0v = (gemm_id == 1) ? bias[row] : 0.f;
        const float b1v = (gemm_id == 1) ? bias[row + 8] : 0.f;
#pragma unroll
        for (int j = 0; j < 4; j++) {
            const int col = n0 + wn * 32 + j * 8 + (lane & 3) * 2;
            float v0x = acc[i][j][0] + b0v, v0y = acc[i][j][1] + b0v;
            float v1x = acc[i][j][2] + b1v, v1y = acc[i][j][3] + b1v;
            s += (v0x + v0y) + (v1x + v1y);
            s2 += v0x * v0x + v0y * v0y + v1x * v1x + v1y * v1y;
            if (qk) {
                *(uint32_t*)(g_Yqk + (size_t)row * NTOK + col) = pack2bf(v0x, v0y);
                *(uint32_t*)(g_Yqk + (size_t)(row + 8) * NTOK + col) = pack2bf(v1x, v1y);
            } else if (gemm_id == 0) {
                float* vout = g_Yv + (size_t)(row - 512) * NTOK;
                *(float2*)(vout + col) = make_float2(v0x, v0y);
                *(float2*)(vout + (size_t)8 * NTOK + col) = make_float2(v1x, v1y);
            } else {
                *(float2*)(out + (size_t)row * NTOK + col) = make_float2(v0x, v0y);
                *(float2*)(out + (size_t)(row + 8) * NTOK + col) = make_float2(v1x, v1y);
            }
        }
    }

    int slot = (gemm_id == 0) ? (qk ? (int)(blockIdx.y >> 1) : -1) : 2;
    if (slot < 0) return;
    const int group_base = (gemm_id == 0) ? (blockIdx.y & 1) * 4 : blockIdx.y * 4;

#pragma unroll
    for (int off = 16; off > 0; off >>= 1) {
        s += __shfl_xor_sync(0xffffffffu, s, off);
        s2 += __shfl_xor_sync(0xffffffffu, s2, off);
    }
    if (lane == 0) { sred[wid][0] = s; sred[wid][1] = s2; }
    __syncthreads();
    if (tid < 4) {
        const int g = tid;
        float ss = 0.f, ss2 = 0.f;
#pragma unroll
        for (int w = 0; w < 4; w++) {
            ss += sred[g * 4 + w][0];
            ss2 += sred[g * 4 + w][1];
        }
        const int b = blockIdx.x >> 5;
        const int bxl = blockIdx.x & 31;
        const int pair = b * 8 + group_base + g;
        g_part[slot][pair][bxl][0] = ss;
        g_part[slot][pair][bxl][1] = ss2;
    }
}

// ---------------- fused dwconv 3x3 + GeLU + conv 3x3: 4x4 patch/thread ---------
__global__ __launch_bounds__(256) void dwconv_fused_kernel(
    const float* __restrict__ x,
    const float* __restrict__ dw1, const float* __restrict__ db1,
    const float* __restrict__ dw2, const float* __restrict__ db2) {
    __shared__ float xs[66 * 68];
    __shared__ float p1[66 * 68];
    const int bc = blockIdx.x;          // b*256 + c
    const int c = bc & 255;
    const float* xb = x + (size_t)bc * HWN;
    const int tid = threadIdx.x;
    const int tx4 = (tid & 15) * 4;
    const int ty4 = (tid >> 4) * 4;

#pragma unroll
    for (int i = tid; i < 66 * 68; i += 256) { xs[i] = 0.f; p1[i] = 0.f; }
    float w1[9], w2[9];
#pragma unroll
    for (int i = 0; i < 9; i++) { w1[i] = dw1[c * 9 + i]; w2[i] = dw2[c * 9 + i]; }
    const float b1 = db1[c], b2 = db2[c];
    __syncthreads();

#pragma unroll
    for (int i = 0; i < 4; i++) {
        int idx = tid + i * 256;
        int py = idx >> 4, px4 = idx & 15;
        float4 v = *(const float4*)(xb + idx * 4);
        float* d = &xs[(py + 1) * 68 + 1 + px4 * 4];
        d[0] = v.x; d[1] = v.y; d[2] = v.z; d[3] = v.w;
    }
    __syncthreads();

    {
        float r[6][6];
#pragma unroll
        for (int rr = 0; rr < 6; rr++) {
            const float* base = &xs[(ty4 + rr) * 68 + tx4];
            *(float4*)&r[rr][0] = *(const float4*)(base);
            *(float2*)&r[rr][4] = *(const float2*)(base + 4);
        }
#pragma unroll
        for (int orow = 0; orow < 4; orow++) {
            float* prow = &p1[(ty4 + orow + 1) * 68 + tx4 + 1];
#pragma unroll
            for (int p = 0; p < 4; p++) {
                float acc = b1;
                acc = fmaf(r[orow][p],         w1[0], acc);
                acc = fmaf(r[orow][p + 1],     w1[1], acc);
                acc = fmaf(r[orow][p + 2],     w1[2], acc);
                acc = fmaf(r[orow + 1][p],     w1[3], acc);
                acc = fmaf(r[orow + 1][p + 1], w1[4], acc);
                acc = fmaf(r[orow + 1][p + 2], w1[5], acc);
                acc = fmaf(r[orow + 2][p],     w1[6], acc);
                acc = fmaf(r[orow + 2][p + 1], w1[7], acc);
                acc = fmaf(r[orow + 2][p + 2], w1[8], acc);
                prow[p] = 0.5f * acc * (1.f + erff(acc * 0.70710678118654752f));
            }
        }
    }
    __syncthreads();

    {
        float r[6][6];
#pragma unroll
        for (int rr = 0; rr < 6; rr++) {
            const float* base = &p1[(ty4 + rr) * 68 + tx4];
            *(float4*)&r[rr][0] = *(const float4*)(base);
            *(float2*)&r[rr][4] = *(const float2*)(base + 4);
        }
#pragma unroll
        for (int orow = 0; orow < 4; orow++) {
            float4 ov;
            float* po = &ov.x;
#pragma unroll
            for (int p = 0; p < 4; p++) {
                float acc = b2;
                acc = fmaf(r[orow][p],         w2[0], acc);
                acc = fmaf(r[orow][p + 1],     w2[1], acc);
                acc = fmaf(r[orow][p + 2],     w2[2], acc);
                acc = fmaf(r[orow + 1][p],     w2[3], acc);
                acc = fmaf(r[orow + 1][p + 1], w2[4], acc);
                acc = fmaf(r[orow + 1][p + 2], w2[5], acc);
                acc = fmaf(r[orow + 2][p],     w2[6], acc);
                acc = fmaf(r[orow + 2][p + 1], w2[7], acc);
                acc = fmaf(r[orow + 2][p + 2], w2[8], acc);
                po[p] = acc;
            }
            *(float4*)(g_pos + (size_t)bc * HWN + (ty4 + orow) * 64 + tx4) = ov;
        }
    }
}

// ---------------- attention: degree-3 moments, bf16 q/k smem -------------------
__global__ __launch_bounds__(512) void attn_kernel(
    const float* __restrict__ gqg, const float* __restrict__ gqb,
    const float* __restrict__ gkg, const float* __restrict__ gkb) {
    extern __shared__ char smraw[];
    unsigned short* smqk = (unsigned short*)smraw;           // [2][256*ATPB]
    float* smv = (float*)(smraw + 2 * 256 * ATPB * 2);       // [256*ATP]
    float* smp = smv + 256 * ATP;                            // [256*ATP]
    __shared__ float sstat[2][8][2];
    const int tid = threadIdx.x;
    const int warp = tid >> 5;        // 0..15 = token
    const int lane = tid & 31;
    const int n0 = blockIdx.x * 16;
    const int b = n0 >> 12;
    const int hw0 = n0 & 4095;

    if (warp < 16) {
        const int sl = warp >> 3;
        const int h = warp & 7;
        float s = g_part[sl][b * 8 + h][lane][0];
        float s2 = g_part[sl][b * 8 + h][lane][1];
#pragma unroll
        for (int off = 16; off > 0; off >>= 1) {
            s += __shfl_xor_sync(0xffffffffu, s, off);
            s2 += __shfl_xor_sync(0xffffffffu, s2, off);
        }
        if (lane == 0) {
            const float inv = 1.f / 131072.f;
            float mean = s * inv;
            float var = s2 * inv - mean * mean;
            sstat[sl][h][0] = mean;
            sstat[sl][h][1] = rsqrtf(var + EPS_GN);
        }
    }

#pragma unroll
    for (int r = 0; r < 2; r++) {
        int slot = tid + r * 512;
        int tens = slot >> 9;
        int row = (slot >> 1) & 255;
        int half = (slot & 1) * 8;
        uint4 u = *(const uint4*)(g_Yqk + (size_t)(tens * 256 + row) * NTOK + n0 + half);
        uint32_t* d = (uint32_t*)(smqk + tens * (256 * ATPB) + row * ATPB + half);
        d[0] = u.x; d[1] = u.y; d[2] = u.z; d[3] = u.w;
    }
#pragma unroll
    for (int r = 0; r < 2; r++) {
        int slot = tid + r * 512;
        int row = slot >> 2;
        int q4 = (slot & 3) * 4;
        float4 v = *(const float4*)(g_Yv + (size_t)row * NTOK + n0 + q4);
        float* dst = smv + row * ATP + q4;
        dst[0] = v.x; dst[1] = v.y; dst[2] = v.z; dst[3] = v.w;
    }
#pragma unroll
    for (int r = 0; r < 2; r++) {
        int slot = tid + r * 512;
        int row = slot >> 2;
        int q4 = (slot & 3) * 4;
        float4 v = *(const float4*)(g_pos + (size_t)b * CHW + (size_t)row * HWN + hw0 + q4);
        float* dst = smp + row * ATP + q4;
        dst[0] = v.x; dst[1] = v.y; dst[2] = v.z; dst[3] = v.w;
    }
    __syncthreads();

    const float scale = 0.17677669529663687f;  // 1/sqrt(32)
    float oacc[8];
#pragma unroll 1
    for (int h = 0; h < 8; h++) {
        const int c = h * 32 + lane;
        float q = us2f(smqk[c * ATPB + warp]);
        float k = us2f(smqk[256 * ATPB + c * ATPB + warp]);
        float vv = smv[c * ATP + warp];
        q = (q - sstat[0][h][0]) * sstat[0][h][1] * gqg[c] + gqb[c];
        k = (k - sstat[1][h][0]) * sstat[1][h][1] * gkg[c] + gkb[c];

        const float k2 = k * k;
        const float k3 = k2 * k;
        float sq = q * q;
        float m1 = k, m2 = k2, m3 = k3;
        float w0 = vv, w1 = k * vv, w2 = k2 * vv, w3 = k3 * vv;
#pragma unroll
        for (int off = 16; off > 0; off >>= 1) {
            sq += __shfl_xor_sync(0xffffffffu, sq, off);
            m1 += __shfl_xor_sync(0xffffffffu, m1, off);
            m2 += __shfl_xor_sync(0xffffffffu, m2, off);
            m3 += __shfl_xor_sync(0xffffffffu, m3, off);
            w0 += __shfl_xor_sync(0xffffffffu, w0, off);
            w1 += __shfl_xor_sync(0xffffffffu, w1, off);
            w2 += __shfl_xor_sync(0xffffffffu, w2, off);
            w3 += __shfl_xor_sync(0xffffffffu, w3, off);
        }
        const float rq = 1.f / fmaxf(sqrtf(sq), 1e-12f);
        const float rk = 1.f / fmaxf(sqrtf(m2), 1e-12f);
        const float rk2 = rk * rk, rk3 = rk2 * rk;
        const float s = q * rq * scale;

        const float c2 = 0.5f, c3 = 1.f / 6.f;
        const float a1 = m1 * rk, a2 = m2 * rk2, a3 = m3 * rk3;
        const float b1m = w1 * rk, b2 = w2 * rk2, b3 = w3 * rk3;
        float num = fmaf(s, fmaf(s, fmaf(s, b3 * c3, b2 * c2), b1m), w0);
        float den = fmaf(s, fmaf(s, fmaf(s, a3 * c3, a2 * c2), a1), 32.f);
        oacc[h] = __fdividef(num, den) + smp[c * ATP + warp];
    }
#pragma unroll
    for (int h = 0; h < 8; h++) smv[(h * 32 + lane) * ATP + warp] = oacc[h];
    __syncthreads();

#pragma unroll
    for (int it = 0; it < 2; it++) {
        const int idx = tid + it * 512;
        const int j = idx >> 6;
        const int c0 = (idx & 63) * 4;
        float f0 = smv[(c0 + 0) * ATP + j];
        float f1 = smv[(c0 + 1) * ATP + j];
        float f2 = smv[(c0 + 2) * ATP + j];
        float f3 = smv[(c0 + 3) * ATP + j];
        ushort4 hs, ls;
        hs.x = f2bf_us(f0); hs.y = f2bf_us(f1); hs.z = f2bf_us(f2); hs.w = f2bf_us(f3);
        ls.x = f2bf_us(f0 - __bfloat162float(__float2bfloat16(f0)));
        ls.y = f2bf_us(f1 - __bfloat162float(__float2bfloat16(f1)));
        ls.z = f2bf_us(f2 - __bfloat162float(__float2bfloat16(f2)));
        ls.w = f2bf_us(f3 - __bfloat162float(__float2bfloat16(f3)));
        const size_t n = (size_t)(n0 + j);
        *(ushort4*)(g_Uhi + n * 256 + c0) = hs;
        *(ushort4*)(g_Ulo + n * 256 + c0) = ls;
    }
}

// ---------------- final GN apply (stats reduced in-block) ----------------------
__global__ void gn_apply_kernel(const float* __restrict__ gamma,
                                const float* __restrict__ beta,
                                float* __restrict__ out) {
    __shared__ float sms[2];
    const int blk0 = blockIdx.x * 256;
    const int cB = blk0 >> 12;
    const int bB = ((blk0 & 4095) * 4) >> 12;
    if (threadIdx.x < 32) {
        const int lane = threadIdx.x;
        const int pair = bB * 8 + (cB >> 5);
        float s = g_part[2][pair][lane][0];
        float s2 = g_part[2][pair][lane][1];
#pragma unroll
        for (int off = 16; off > 0; off >>= 1) {
            s += __shfl_xor_sync(0xffffffffu, s, off);
            s2 += __shfl_xor_sync(0xffffffffu, s2, off);
        }
        if (lane == 0) {
            const float inv = 1.f / 131072.f;
            float mean = s * inv;
            float var = s2 * inv - mean * mean;
            sms[0] = mean;
            sms[1] = rsqrtf(var + EPS_GN);
        }
    }
    __syncthreads();
    const int idx4 = blk0 + threadIdx.x;
    const int c = idx4 >> 12;
    const int n = (idx4 & 4095) * 4;
    const int b = n >> 12;
    const float mean = sms[0], rstd = sms[1];
    const float ga = gamma[c], be = beta[c];
    float4 v = *(const float4*)(g_Z + (size_t)idx4 * 4);
    v.x = (v.x - mean) * rstd * ga + be;
    v.y = (v.y - mean) * rstd * ga + be;
    v.z = (v.z - mean) * rstd * ga + be;
    v.w = (v.w - mean) * rstd * ga + be;
    *(float4*)(out + (size_t)b * CHW + (size_t)c * HWN + (n & 4095)) = v;
}

// ---------------- launcher -----------------------------------------------------
extern "C" void kernel_launch(void* const* d_in, const int* in_sizes, int n_in,
                              void* d_out, int out_size) {
    const float* x        = (const float*)d_in[0];
    const float* wq       = (const float*)d_in[1];
    const float* gq_gamma = (const float*)d_in[2];
    const float* gq_beta  = (const float*)d_in[3];
    const float* wk       = (const float*)d_in[4];
    const float* gk_gamma = (const float*)d_in[5];
    const float* gk_beta  = (const float*)d_in[6];
    const float* wv       = (const float*)d_in[7];
    const float* wp       = (const float*)d_in[8];
    const float* bp       = (const float*)d_in[9];
    const float* gp_gamma = (const float*)d_in[10];
    const float* gp_beta  = (const float*)d_in[11];
    const float* dw1      = (const float*)d_in[12];
    const float* db1      = (const float*)d_in[13];
    const float* dw2      = (const float*)d_in[14];
    const float* db2      = (const float*)d_in[15];
    float* out = (float*)d_out;

    const int GEMM_SMEM = 2 * 4 * 128 * LDT * 2;                   // 81920
    const int ATTN_SMEM = 2 * 256 * ATPB * 2 + 2 * 256 * ATP * 4;  // 53248

    static cudaStream_t s1;
    static cudaEvent_t evStart, evW, evD;
    static bool init_done = false;
    if (!init_done) {
        cudaFuncSetAttribute(attn_kernel, cudaFuncAttributeMaxDynamicSharedMemorySize, ATTN_SMEM);
        cudaFuncSetAttribute(mma_gemm_kernel, cudaFuncAttributeMaxDynamicSharedMemorySize, GEMM_SMEM);
        cudaStreamCreateWithFlags(&s1, cudaStreamNonBlocking);
        cudaEventCreateWithFlags(&evStart, cudaEventDisableTiming);
        cudaEventCreateWithFlags(&evW, cudaEventDisableTiming);
        cudaEventCreateWithFlags(&evD, cudaEventDisableTiming);
        init_done = true;
    }

    float *g_Z_p;
    __nv_bfloat16 *whi, *wlo, *wphi, *wplo, *xhi, *xlo, *uhi, *ulo;
    cudaGetSymbolAddress((void**)&g_Z_p, g_Z);
    cudaGetSymbolAddress((void**)&whi, g_Whi);
    cudaGetSymbolAddress((void**)&wlo, g_Wlo);
    cudaGetSymbolAddress((void**)&wphi, g_Wphi);
    cudaGetSymbolAddress((void**)&wplo, g_Wplo);
    cudaGetSymbolAddress((void**)&xhi, g_Xhi);
    cudaGetSymbolAddress((void**)&xlo, g_Xlo);
    cudaGetSymbolAddress((void**)&uhi, g_Uhi);
    cudaGetSymbolAddress((void**)&ulo, g_Ulo);

    // fork side stream s1 off main stream
    cudaEventRecord(evStart, 0);
    cudaStreamWaitEvent(s1, evStart, 0);

    // s1: weight conversion (feeds GEMM1), then independent dwconv path
    convert_w_kernel<<<1024, 256, 0, s1>>>(wq, wk, wv, wp);
    cudaEventRecord(evW, s1);
    dwconv_fused_kernel<<<1024, 256, 0, s1>>>(x, dw1, db1, dw2, db2);
    cudaEventRecord(evD, s1);

    // s0: transpose (independent of weights), then GEMM1 after weights ready
    transpose_convert_kernel<<<dim3(128, 8, BATCH), 256>>>(x, HWN, CHW, xhi, xlo);
    cudaStreamWaitEvent(0, evW, 0);
    mma_gemm_kernel<<<dim3(128, 6), 512, GEMM_SMEM>>>(whi, wlo, xhi, xlo, nullptr, nullptr, 0);
    // attn needs dwconv output
    cudaStreamWaitEvent(0, evD, 0);
    attn_kernel<<<1024, 512, ATTN_SMEM>>>(gq_gamma, gq_beta, gk_gamma, gk_beta);
    mma_gemm_kernel<<<dim3(128, 2), 512, GEMM_SMEM>>>(wphi, wplo, uhi, ulo, g_Z_p, bp, 1);
    gn_apply_kernel<<<NTOK * 256 / 1024, 256>>>(gp_gamma, gp_beta, out);
}

// round 17
// speedup vs baseline: 1.2269x; 1.0674x over previous
#include <cuda_runtime.h>
#include <cuda_bf16.h>
#include <cuda_fp16.h>
#include <math.h>
#include <stdint.h>

#define BATCH 4
#define CCH 256
#define HWN 4096
#define NTOK 16384          // BATCH*HWN
#define CHW (CCH*HWN)
#define TOTAL (BATCH*CHW)
#define EPS_GN 1e-5f
#define LDT 40              // padded smem row length (fp16) for 32-wide K tile
#define NPART 32            // n-tiles per batch (4096/128)
#define ATP 17              // attn fp32 smem col pad (16 tokens + 1)
#define ATPB 18             // attn bf16 smem col pad

// ---------------- scratch (device globals) ------------------------------------
__device__ __nv_bfloat16 g_Yqk[(size_t)512 * NTOK];  // rows 0-255 q, 256-511 k (bf16)
__device__ float g_Yv[(size_t)256 * NTOK];           // v fp32 channel-major
__device__ float g_pos[TOTAL];                       // NCHW positional branch output
__device__ float g_Z[(size_t)CCH * NTOK];            // [256][16384] channel-major
__device__ float g_part[3][32][NPART][2];            // stats partials from GEMM epilogues
__device__ __half g_Whi[768 * 256], g_Wlo[768 * 256];
__device__ __half g_Wphi[256 * 256], g_Wplo[256 * 256];
__device__ __half g_Xhi[(size_t)NTOK * 256], g_Xlo[(size_t)NTOK * 256];
__device__ __half g_Uhi[(size_t)NTOK * 256], g_Ulo[(size_t)NTOK * 256];

// ---------------- helpers ------------------------------------------------------
__device__ __forceinline__ uint32_t smem_u32(const void* p) {
    return (uint32_t)__cvta_generic_to_shared(p);
}
__device__ __forceinline__ unsigned short f2bf_us(float v) {
    __nv_bfloat16 b = __float2bfloat16(v);
    return *reinterpret_cast<unsigned short*>(&b);
}
__device__ __forceinline__ float us2f(unsigned short u) {
    __nv_bfloat16 b = *reinterpret_cast<__nv_bfloat16*>(&u);
    return __bfloat162float(b);
}
__device__ __forceinline__ unsigned short f2h_us(float v) {
    __half h = __float2half(v);
    return *reinterpret_cast<unsigned short*>(&h);
}
__device__ __forceinline__ uint32_t pack2bf(float a, float b) {
    return ((uint32_t)f2bf_us(b) << 16) | f2bf_us(a);
}
__device__ __forceinline__ void cp_async16(uint32_t s, const void* g) {
    asm volatile("cp.async.cg.shared.global [%0], [%1], 16;" :: "r"(s), "l"(g));
}
__device__ __forceinline__ void cp_commit() {
    asm volatile("cp.async.commit_group;");
}
__device__ __forceinline__ void ldsm_x4(uint32_t* r, uint32_t a) {
    asm volatile("ldmatrix.sync.aligned.m8n8.x4.shared.b16 {%0,%1,%2,%3}, [%4];"
                 : "=r"(r[0]), "=r"(r[1]), "=r"(r[2]), "=r"(r[3]) : "r"(a));
}
__device__ __forceinline__ void mma_f16(float* c, const uint32_t* a, const uint32_t* b) {
    asm volatile(
        "mma.sync.aligned.m16n8k16.row.col.f32.f16.f16.f32 "
        "{%0,%1,%2,%3}, {%4,%5,%6,%7}, {%8,%9}, {%0,%1,%2,%3};"
        : "+f"(c[0]), "+f"(c[1]), "+f"(c[2]), "+f"(c[3])
        : "r"(a[0]), "r"(a[1]), "r"(a[2]), "r"(a[3]), "r"(b[0]), "r"(b[1]));
}

// ---------------- W -> fp16 hi/lo (K-major already) ----------------------------
__global__ void convert_w_kernel(const float* __restrict__ wq, const float* __restrict__ wk,
                                 const float* __restrict__ wv, const float* __restrict__ wp) {
    int i = blockIdx.x * 256 + threadIdx.x;  // 0..262143
    float v;
    __half *hi, *lo;
    int o;
    if (i < 65536)        { v = wq[i];          o = i;          hi = g_Whi;  lo = g_Wlo; }
    else if (i < 131072)  { v = wk[i - 65536];  o = i;          hi = g_Whi;  lo = g_Wlo; }
    else if (i < 196608)  { v = wv[i - 131072]; o = i;          hi = g_Whi;  lo = g_Wlo; }
    else                  { v = wp[i - 196608]; o = i - 196608; hi = g_Wphi; lo = g_Wplo; }
    __half h = __float2half(v);
    hi[o] = h;
    lo[o] = __float2half(v - __half2float(h));
}

// ---------------- transpose [c][hw] fp32 -> token-major fp16 hi/lo -------------
__global__ void transpose_convert_kernel(const float* __restrict__ src, int c_stride, int b_stride,
                                         __half* __restrict__ dhi,
                                         __half* __restrict__ dlo) {
    __shared__ float t[32][33];
    const int hw0 = blockIdx.x * 32, c0 = blockIdx.y * 32, b = blockIdx.z;
    const int tid = threadIdx.x;
    const int rl = tid >> 3, q = tid & 7;
    float4 v = *(const float4*)(src + (size_t)b * b_stride + (size_t)(c0 + rl) * c_stride + hw0 + q * 4);
    t[rl][q * 4 + 0] = v.x; t[rl][q * 4 + 1] = v.y;
    t[rl][q * 4 + 2] = v.z; t[rl][q * 4 + 3] = v.w;
    __syncthreads();
    const int n = b * HWN + hw0 + rl;
    float f0 = t[q * 4 + 0][rl], f1 = t[q * 4 + 1][rl];
    float f2 = t[q * 4 + 2][rl], f3 = t[q * 4 + 3][rl];
    ushort4 hs, ls;
    hs.x = f2h_us(f0); hs.y = f2h_us(f1); hs.z = f2h_us(f2); hs.w = f2h_us(f3);
    ls.x = f2h_us(f0 - __half2float(__float2half(f0)));
    ls.y = f2h_us(f1 - __half2float(__float2half(f1)));
    ls.z = f2h_us(f2 - __half2float(__float2half(f2)));
    ls.w = f2h_us(f3 - __half2float(__float2half(f3)));
    *(ushort4*)(dhi + (size_t)n * 256 + c0 + q * 4) = hs;
    *(ushort4*)(dlo + (size_t)n * 256 + c0 + q * 4) = ls;
}

// ---------------- mma.sync fp16 GEMM, 16 warps x 32x32 warp tile ---------------
// gemm1 (id 0): ALL blocks single fp16 pass. q,k -> g_Yqk bf16; v -> g_Yv fp32.
// gemm2 (id 1): 3-pass fp16 hi/lo split -> out (+bias).
__global__ __launch_bounds__(512, 2) void mma_gemm_kernel(
    const __half* __restrict__ Ahi, const __half* __restrict__ Alo,
    const __half* __restrict__ Bhi, const __half* __restrict__ Blo,
    float* __restrict__ out, const float* __restrict__ bias, int gemm_id) {
    extern __shared__ __half smT[];   // [2 buf][4 mat][128*LDT]
    __shared__ float sred[16][2];
    const int tid = threadIdx.x;
    const int lane = tid & 31;
    const int wid = tid >> 5;         // 0..15
    const int wm = wid >> 2;          // 0..3 (32 rows each)
    const int wn = wid & 3;           // 0..3 (32 cols each)
    const int m0 = blockIdx.y * 128;
    const int n0 = blockIdx.x * 128;
    const int qk = (gemm_id == 0 && blockIdx.y < 4);
    const int npass = (gemm_id == 0) ? 1 : 3;

    float acc[2][4][4];
#pragma unroll
    for (int i = 0; i < 2; i++)
#pragma unroll
        for (int j = 0; j < 4; j++)
#pragma unroll
            for (int r = 0; r < 4; r++) acc[i][j][r] = 0.f;

    const int lrow = tid >> 2;            // 0..127
    const int lch = tid & 3;              // 16B chunk 0..3

#define TILE_BASE(buf, mat) (smT + ((buf) * 4 + (mat)) * (128 * LDT))
#define LOAD_STAGE(buf, kc)                                                             \
    do {                                                                                \
        const int k0 = (kc) * 32;                                                       \
        _Pragma("unroll")                                                               \
        for (int mat = 0; mat < 4; mat++) {                                             \
            if (npass == 1 && (mat == 1 || mat == 3)) continue;                         \
            const __half* src =                                                         \
                ((mat == 0) ? Ahi : (mat == 1) ? Alo : (mat == 2) ? Bhi : Blo) +        \
                (size_t)(((mat < 2) ? m0 : n0) + lrow) * 256 + k0 + lch * 8;            \
            cp_async16(smem_u32(TILE_BASE(buf, mat) + lrow * LDT + lch * 8), src);      \
        }                                                                               \
        cp_commit();                                                                    \
    } while (0)

    LOAD_STAGE(0, 0);

    int buf = 0;
    for (int kc = 0; kc < 8; kc++) {
        if (kc + 1 < 8) {
            LOAD_STAGE(buf ^ 1, kc + 1);
            asm volatile("cp.async.wait_group 1;");
        } else {
            asm volatile("cp.async.wait_group 0;");
        }
        __syncthreads();

#pragma unroll 3
        for (int pass = 0; pass < npass; pass++) {
            const __half* At = TILE_BASE(buf, (pass == 2) ? 1 : 0);
            const __half* Bt = TILE_BASE(buf, (pass == 1) ? 3 : 2);
#pragma unroll
            for (int ks = 0; ks < 2; ks++) {
                uint32_t afr[2][4];
#pragma unroll
                for (int i = 0; i < 2; i++) {
                    uint32_t a = smem_u32(&At[(wm * 32 + i * 16 + (lane & 15)) * LDT +
                                             ((lane >> 4) * 8 + ks * 16)]);
                    ldsm_x4(afr[i], a);
                }
                uint32_t bfr[4][2];
#pragma unroll
                for (int jp = 0; jp < 2; jp++) {
                    uint32_t a = smem_u32(&Bt[(wn * 32 + (jp * 2 + ((lane >> 4) & 1)) * 8 +
                                              (lane & 7)) * LDT +
                                             (((lane >> 3) & 1) * 8 + ks * 16)]);
                    uint32_t r[4];
                    ldsm_x4(r, a);
                    bfr[jp * 2][0] = r[0]; bfr[jp * 2][1] = r[1];
                    bfr[jp * 2 + 1][0] = r[2]; bfr[jp * 2 + 1][1] = r[3];
                }
#pragma unroll
                for (int i = 0; i < 2; i++)
#pragma unroll
                    for (int j = 0; j < 4; j++) mma_f16(acc[i][j], afr[i], bfr[j]);
            }
        }
        __syncthreads();
        buf ^= 1;
    }
#undef LOAD_STAGE
#undef TILE_BASE

    // epilogue: stores + per-warp GN stats (warp's 32 rows = one group g=wm)
    float s = 0.f, s2 = 0.f;
#pragma unroll
    for (int i = 0; i < 2; i++) {
        const int row = m0 + wm * 32 + i * 16 + (lane >> 2);
        const float b0v = (gemm_id == 1) ? bias[row] : 0.f;
        const float b1v = (gemm_id == 1) ? bias[row + 8] : 0.f;
#pragma unroll
        for (int j = 0; j < 4; j++) {
            const int col = n0 + wn * 32 + j * 8 + (lane & 3) * 2;
            float v0x = acc[i][j][0] + b0v, v0y = acc[i][j][1] + b0v;
            float v1x = acc[i][j][2] + b1v, v1y = acc[i][j][3] + b1v;
            s += (v0x + v0y) + (v1x + v1y);
            s2 += v0x * v0x + v0y * v0y + v1x * v1x + v1y * v1y;
            if (qk) {
                *(uint32_t*)(g_Yqk + (size_t)row * NTOK + col) = pack2bf(v0x, v0y);
                *(uint32_t*)(g_Yqk + (size_t)(row + 8) * NTOK + col) = pack2bf(v1x, v1y);
            } else if (gemm_id == 0) {
                float* vout = g_Yv + (size_t)(row - 512) * NTOK;
                *(float2*)(vout + col) = make_float2(v0x, v0y);
                *(float2*)(vout + (size_t)8 * NTOK + col) = make_float2(v1x, v1y);
            } else {
                *(float2*)(out + (size_t)row * NTOK + col) = make_float2(v0x, v0y);
                *(float2*)(out + (size_t)(row + 8) * NTOK + col) = make_float2(v1x, v1y);
            }
        }
    }

    int slot = (gemm_id == 0) ? (qk ? (int)(blockIdx.y >> 1) : -1) : 2;
    if (slot < 0) return;
    const int group_base = (gemm_id == 0) ? (blockIdx.y & 1) * 4 : blockIdx.y * 4;

#pragma unroll
    for (int off = 16; off > 0; off >>= 1) {
        s += __shfl_xor_sync(0xffffffffu, s, off);
        s2 += __shfl_xor_sync(0xffffffffu, s2, off);
    }
    if (lane == 0) { sred[wid][0] = s; sred[wid][1] = s2; }
    __syncthreads();
    if (tid < 4) {
        const int g = tid;
        float ss = 0.f, ss2 = 0.f;
#pragma unroll
        for (int w = 0; w < 4; w++) {
            ss += sred[g * 4 + w][0];
            ss2 += sred[g * 4 + w][1];
        }
        const int b = blockIdx.x >> 5;
        const int bxl = blockIdx.x & 31;
        const int pair = b * 8 + group_base + g;
        g_part[slot][pair][bxl][0] = ss;
        g_part[slot][pair][bxl][1] = ss2;
    }
}

// ---------------- fused dwconv 3x3 + GeLU + conv 3x3: 4x4 patch/thread ---------
__global__ __launch_bounds__(256) void dwconv_fused_kernel(
    const float* __restrict__ x,
    const float* __restrict__ dw1, const float* __restrict__ db1,
    const float* __restrict__ dw2, const float* __restrict__ db2) {
    __shared__ float xs[66 * 68];
    __shared__ float p1[66 * 68];
    const int bc = blockIdx.x;          // b*256 + c
    const int c = bc & 255;
    const float* xb = x + (size_t)bc * HWN;
    const int tid = threadIdx.x;
    const int tx4 = (tid & 15) * 4;
    const int ty4 = (tid >> 4) * 4;

#pragma unroll
    for (int i = tid; i < 66 * 68; i += 256) { xs[i] = 0.f; p1[i] = 0.f; }
    float w1[9], w2[9];
#pragma unroll
    for (int i = 0; i < 9; i++) { w1[i] = dw1[c * 9 + i]; w2[i] = dw2[c * 9 + i]; }
    const float b1 = db1[c], b2 = db2[c];
    __syncthreads();

#pragma unroll
    for (int i = 0; i < 4; i++) {
        int idx = tid + i * 256;
        int py = idx >> 4, px4 = idx & 15;
        float4 v = *(const float4*)(xb + idx * 4);
        float* d = &xs[(py + 1) * 68 + 1 + px4 * 4];
        d[0] = v.x; d[1] = v.y; d[2] = v.z; d[3] = v.w;
    }
    __syncthreads();

    {
        float r[6][6];
#pragma unroll
        for (int rr = 0; rr < 6; rr++) {
            const float* base = &xs[(ty4 + rr) * 68 + tx4];
            *(float4*)&r[rr][0] = *(const float4*)(base);
            *(float2*)&r[rr][4] = *(const float2*)(base + 4);
        }
#pragma unroll
        for (int orow = 0; orow < 4; orow++) {
            float* prow = &p1[(ty4 + orow + 1) * 68 + tx4 + 1];
#pragma unroll
            for (int p = 0; p < 4; p++) {
                float acc = b1;
                acc = fmaf(r[orow][p],         w1[0], acc);
                acc = fmaf(r[orow][p + 1],     w1[1], acc);
                acc = fmaf(r[orow][p + 2],     w1[2], acc);
                acc = fmaf(r[orow + 1][p],     w1[3], acc);
                acc = fmaf(r[orow + 1][p + 1], w1[4], acc);
                acc = fmaf(r[orow + 1][p + 2], w1[5], acc);
                acc = fmaf(r[orow + 2][p],     w1[6], acc);
                acc = fmaf(r[orow + 2][p + 1], w1[7], acc);
                acc = fmaf(r[orow + 2][p + 2], w1[8], acc);
                prow[p] = 0.5f * acc * (1.f + erff(acc * 0.70710678118654752f));
            }
        }
    }
    __syncthreads();

    {
        float r[6][6];
#pragma unroll
        for (int rr = 0; rr < 6; rr++) {
            const float* base = &p1[(ty4 + rr) * 68 + tx4];
            *(float4*)&r[rr][0] = *(const float4*)(base);
            *(float2*)&r[rr][4] = *(const float2*)(base + 4);
        }
#pragma unroll
        for (int orow = 0; orow < 4; orow++) {
            float4 ov;
            float* po = &ov.x;
#pragma unroll
            for (int p = 0; p < 4; p++) {
                float acc = b2;
                acc = fmaf(r[orow][p],         w2[0], acc);
                acc = fmaf(r[orow][p + 1],     w2[1], acc);
                acc = fmaf(r[orow][p + 2],     w2[2], acc);
                acc = fmaf(r[orow + 1][p],     w2[3], acc);
                acc = fmaf(r[orow + 1][p + 1], w2[4], acc);
                acc = fmaf(r[orow + 1][p + 2], w2[5], acc);
                acc = fmaf(r[orow + 2][p],     w2[6], acc);
                acc = fmaf(r[orow + 2][p + 1], w2[7], acc);
                acc = fmaf(r[orow + 2][p + 2], w2[8], acc);
                po[p] = acc;
            }
            *(float4*)(g_pos + (size_t)bc * HWN + (ty4 + orow) * 64 + tx4) = ov;
        }
    }
}

// ---------------- attention: degree-3 moments, bf16 q/k smem -------------------
__global__ __launch_bounds__(512) void attn_kernel(
    const float* __restrict__ gqg, const float* __restrict__ gqb,
    const float* __restrict__ gkg, const float* __restrict__ gkb) {
    extern __shared__ char smraw[];
    unsigned short* smqk = (unsigned short*)smraw;           // [2][256*ATPB]
    float* smv = (float*)(smraw + 2 * 256 * ATPB * 2);       // [256*ATP]
    float* smp = smv + 256 * ATP;                            // [256*ATP]
    __shared__ float sstat[2][8][2];
    const int tid = threadIdx.x;
    const int warp = tid >> 5;        // 0..15 = token
    const int lane = tid & 31;
    const int n0 = blockIdx.x * 16;
    const int b = n0 >> 12;
    const int hw0 = n0 & 4095;

    if (warp < 16) {
        const int sl = warp >> 3;
        const int h = warp & 7;
        float s = g_part[sl][b * 8 + h][lane][0];
        float s2 = g_part[sl][b * 8 + h][lane][1];
#pragma unroll
        for (int off = 16; off > 0; off >>= 1) {
            s += __shfl_xor_sync(0xffffffffu, s, off);
            s2 += __shfl_xor_sync(0xffffffffu, s2, off);
        }
        if (lane == 0) {
            const float inv = 1.f / 131072.f;
            float mean = s * inv;
            float var = s2 * inv - mean * mean;
            sstat[sl][h][0] = mean;
            sstat[sl][h][1] = rsqrtf(var + EPS_GN);
        }
    }

#pragma unroll
    for (int r = 0; r < 2; r++) {
        int slot = tid + r * 512;
        int tens = slot >> 9;
        int row = (slot >> 1) & 255;
        int half = (slot & 1) * 8;
        uint4 u = *(const uint4*)(g_Yqk + (size_t)(tens * 256 + row) * NTOK + n0 + half);
        uint32_t* d = (uint32_t*)(smqk + tens * (256 * ATPB) + row * ATPB + half);
        d[0] = u.x; d[1] = u.y; d[2] = u.z; d[3] = u.w;
    }
#pragma unroll
    for (int r = 0; r < 2; r++) {
        int slot = tid + r * 512;
        int row = slot >> 2;
        int q4 = (slot & 3) * 4;
        float4 v = *(const float4*)(g_Yv + (size_t)row * NTOK + n0 + q4);
        float* dst = smv + row * ATP + q4;
        dst[0] = v.x; dst[1] = v.y; dst[2] = v.z; dst[3] = v.w;
    }
#pragma unroll
    for (int r = 0; r < 2; r++) {
        int slot = tid + r * 512;
        int row = slot >> 2;
        int q4 = (slot & 3) * 4;
        float4 v = *(const float4*)(g_pos + (size_t)b * CHW + (size_t)row * HWN + hw0 + q4);
        float* dst = smp + row * ATP + q4;
        dst[0] = v.x; dst[1] = v.y; dst[2] = v.z; dst[3] = v.w;
    }
    __syncthreads();

    const float scale = 0.17677669529663687f;  // 1/sqrt(32)
    float oacc[8];
#pragma unroll 1
    for (int h = 0; h < 8; h++) {
        const int c = h * 32 + lane;
        float q = us2f(smqk[c * ATPB + warp]);
        float k = us2f(smqk[256 * ATPB + c * ATPB + warp]);
        float vv = smv[c * ATP + warp];
        q = (q - sstat[0][h][0]) * sstat[0][h][1] * gqg[c] + gqb[c];
        k = (k - sstat[1][h][0]) * sstat[1][h][1] * gkg[c] + gkb[c];

        const float k2 = k * k;
        const float k3 = k2 * k;
        float sq = q * q;
        float m1 = k, m2 = k2, m3 = k3;
        float w0 = vv, w1 = k * vv, w2 = k2 * vv, w3 = k3 * vv;
#pragma unroll
        for (int off = 16; off > 0; off >>= 1) {
            sq += __shfl_xor_sync(0xffffffffu, sq, off);
            m1 += __shfl_xor_sync(0xffffffffu, m1, off);
            m2 += __shfl_xor_sync(0xffffffffu, m2, off);
            m3 += __shfl_xor_sync(0xffffffffu, m3, off);
            w0 += __shfl_xor_sync(0xffffffffu, w0, off);
            w1 += __shfl_xor_sync(0xffffffffu, w1, off);
            w2 += __shfl_xor_sync(0xffffffffu, w2, off);
            w3 += __shfl_xor_sync(0xffffffffu, w3, off);
        }
        const float rq = 1.f / fmaxf(sqrtf(sq), 1e-12f);
        const float rk = 1.f / fmaxf(sqrtf(m2), 1e-12f);
        const float rk2 = rk * rk, rk3 = rk2 * rk;
        const float s = q * rq * scale;

        const float c2 = 0.5f, c3 = 1.f / 6.f;
        const float a1 = m1 * rk, a2 = m2 * rk2, a3 = m3 * rk3;
        const float b1m = w1 * rk, b2 = w2 * rk2, b3 = w3 * rk3;
        float num = fmaf(s, fmaf(s, fmaf(s, b3 * c3, b2 * c2), b1m), w0);
        float den = fmaf(s, fmaf(s, fmaf(s, a3 * c3, a2 * c2), a1), 32.f);
        oacc[h] = __fdividef(num, den) + smp[c * ATP + warp];
    }
#pragma unroll
    for (int h = 0; h < 8; h++) smv[(h * 32 + lane) * ATP + warp] = oacc[h];
    __syncthreads();

    // emit token-major fp16 hi/lo: U[n][256]
#pragma unroll
    for (int it = 0; it < 2; it++) {
        const int idx = tid + it * 512;
        const int j = idx >> 6;
        const int c0 = (idx & 63) * 4;
        float f0 = smv[(c0 + 0) * ATP + j];
        float f1 = smv[(c0 + 1) * ATP + j];
        float f2 = smv[(c0 + 2) * ATP + j];
        float f3 = smv[(c0 + 3) * ATP + j];
        ushort4 hs, ls;
        hs.x = f2h_us(f0); hs.y = f2h_us(f1); hs.z = f2h_us(f2); hs.w = f2h_us(f3);
        ls.x = f2h_us(f0 - __half2float(__float2half(f0)));
        ls.y = f2h_us(f1 - __half2float(__float2half(f1)));
        ls.z = f2h_us(f2 - __half2float(__float2half(f2)));
        ls.w = f2h_us(f3 - __half2float(__float2half(f3)));
        const size_t n = (size_t)(n0 + j);
        *(ushort4*)(g_Uhi + n * 256 + c0) = hs;
        *(ushort4*)(g_Ulo + n * 256 + c0) = ls;
    }
}

// ---------------- final GN apply (stats reduced in-block) ----------------------
__global__ void gn_apply_kernel(const float* __restrict__ gamma,
                                const float* __restrict__ beta,
                                float* __restrict__ out) {
    __shared__ float sms[2];
    const int blk0 = blockIdx.x * 256;
    const int cB = blk0 >> 12;
    const int bB = ((blk0 & 4095) * 4) >> 12;
    if (threadIdx.x < 32) {
        const int lane = threadIdx.x;
        const int pair = bB * 8 + (cB >> 5);
        float s = g_part[2][pair][lane][0];
        float s2 = g_part[2][pair][lane][1];
#pragma unroll
        for (int off = 16; off > 0; off >>= 1) {
            s += __shfl_xor_sync(0xffffffffu, s, off);
            s2 += __shfl_xor_sync(0xffffffffu, s2, off);
        }
        if (lane == 0) {
            const float inv = 1.f / 131072.f;
            float mean = s * inv;
            float var = s2 * inv - mean * mean;
            sms[0] = mean;
            sms[1] = rsqrtf(var + EPS_GN);
        }
    }
    __syncthreads();
    const int idx4 = blk0 + threadIdx.x;
    const int c = idx4 >> 12;
    const int n = (idx4 & 4095) * 4;
    const int b = n >> 12;
    const float mean = sms[0], rstd = sms[1];
    const float ga = gamma[c], be = beta[c];
    float4 v = *(const float4*)(g_Z + (size_t)idx4 * 4);
    v.x = (v.x - mean) * rstd * ga + be;
    v.y = (v.y - mean) * rstd * ga + be;
    v.z = (v.z - mean) * rstd * ga + be;
    v.w = (v.w - mean) * rstd * ga + be;
    *(float4*)(out + (size_t)b * CHW + (size_t)c * HWN + (n & 4095)) = v;
}

// ---------------- launcher -----------------------------------------------------
extern "C" void kernel_launch(void* const* d_in, const int* in_sizes, int n_in,
                              void* d_out, int out_size) {
    const float* x        = (const float*)d_in[0];
    const float* wq       = (const float*)d_in[1];
    const float* gq_gamma = (const float*)d_in[2];
    const float* gq_beta  = (const float*)d_in[3];
    const float* wk       = (const float*)d_in[4];
    const float* gk_gamma = (const float*)d_in[5];
    const float* gk_beta  = (const float*)d_in[6];
    const float* wv       = (const float*)d_in[7];
    const float* wp       = (const float*)d_in[8];
    const float* bp       = (const float*)d_in[9];
    const float* gp_gamma = (const float*)d_in[10];
    const float* gp_beta  = (const float*)d_in[11];
    const float* dw1      = (const float*)d_in[12];
    const float* db1      = (const float*)d_in[13];
    const float* dw2      = (const float*)d_in[14];
    const float* db2      = (const float*)d_in[15];
    float* out = (float*)d_out;

    const int GEMM_SMEM = 2 * 4 * 128 * LDT * 2;                   // 81920
    const int ATTN_SMEM = 2 * 256 * ATPB * 2 + 2 * 256 * ATP * 4;  // 53248

    static cudaStream_t s1;
    static cudaEvent_t evStart, evW, evD;
    static bool init_done = false;
    if (!init_done) {
        cudaFuncSetAttribute(attn_kernel, cudaFuncAttributeMaxDynamicSharedMemorySize, ATTN_SMEM);
        cudaFuncSetAttribute(mma_gemm_kernel, cudaFuncAttributeMaxDynamicSharedMemorySize, GEMM_SMEM);
        cudaStreamCreateWithFlags(&s1, cudaStreamNonBlocking);
        cudaEventCreateWithFlags(&evStart, cudaEventDisableTiming);
        cudaEventCreateWithFlags(&evW, cudaEventDisableTiming);
        cudaEventCreateWithFlags(&evD, cudaEventDisableTiming);
        init_done = true;
    }

    float *g_Z_p;
    __half *whi, *wlo, *wphi, *wplo, *xhi, *xlo, *uhi, *ulo;
    cudaGetSymbolAddress((void**)&g_Z_p, g_Z);
    cudaGetSymbolAddress((void**)&whi, g_Whi);
    cudaGetSymbolAddress((void**)&wlo, g_Wlo);
    cudaGetSymbolAddress((void**)&wphi, g_Wphi);
    cudaGetSymbolAddress((void**)&wplo, g_Wplo);
    cudaGetSymbolAddress((void**)&xhi, g_Xhi);
    cudaGetSymbolAddress((void**)&xlo, g_Xlo);
    cudaGetSymbolAddress((void**)&uhi, g_Uhi);
    cudaGetSymbolAddress((void**)&ulo, g_Ulo);

    // fork side stream s1 off main stream
    cudaEventRecord(evStart, 0);
    cudaStreamWaitEvent(s1, evStart, 0);

    // s1: weight conversion (feeds GEMM1), then independent dwconv path
    convert_w_kernel<<<1024, 256, 0, s1>>>(wq, wk, wv, wp);
    cudaEventRecord(evW, s1);
    dwconv_fused_kernel<<<1024, 256, 0, s1>>>(x, dw1, db1, dw2, db2);
    cudaEventRecord(evD, s1);

    // s0: transpose (independent of weights), then GEMM1 after weights ready
    transpose_convert_kernel<<<dim3(128, 8, BATCH), 256>>>(x, HWN, CHW, xhi, xlo);
    cudaStreamWaitEvent(0, evW, 0);
    mma_gemm_kernel<<<dim3(128, 6), 512, GEMM_SMEM>>>(whi, wlo, xhi, xlo, nullptr, nullptr, 0);
    // attn needs dwconv output
    cudaStreamWaitEvent(0, evD, 0);
    attn_kernel<<<1024, 512, ATTN_SMEM>>>(gq_gamma, gq_beta, gk_gamma, gk_beta);
    mma_gemm_kernel<<<dim3(128, 2), 512, GEMM_SMEM>>>(wphi, wplo, uhi, ulo, g_Z_p, bp, 1);
    gn_apply_kernel<<<NTOK * 256 / 1024, 256>>>(gp_gamma, gp_beta, out);
}